// round 2
// baseline (speedup 1.0000x reference)
#include <cuda_runtime.h>

#define DIN 768
#define HID 256
#define NN  8192
#define MM  4096
#define OUTFE 50

// Scratch (device globals: no allocations allowed)
__device__ float g_Z[(size_t)MM * DIN];    // gathered AGE rows -> lintrans output
__device__ float g_EW[(size_t)MM * HID];   // tanh(E) * outW
__device__ float g_h[(size_t)NN * HID];    // tanh(t @ W_prjT^T + b)

// ---------------------------------------------------------------------------
// Generic tiled SGEMM:  C[m,n] = epi( sum_k A[row(m),k] * W[n,k] + bias[n] )
//   row(m) = gather ? gather[m] : m     (A is row-major [*,K], W row-major [N,K])
//   EPI: 0 = none, 1 = tanh, 2 = tanh then * mul[m*N+n]
// BM,BN in {64,128}; BK=16; blockDim (16,16)=256 threads; TM=BM/16, TN=BN/16.
// ---------------------------------------------------------------------------
template<int BM, int BN, int TM, int TN, int EPI, bool GATHER>
__global__ void __launch_bounds__(256, 2)
sgemm_nt(const float* __restrict__ A,
         const float* __restrict__ W,
         const float* __restrict__ bias,
         const float* __restrict__ mul,
         float* __restrict__ C,
         int N, int K,
         const int* __restrict__ gather)
{
    constexpr int BK = 16;
    __shared__ float As[BK][BM];
    __shared__ float Bs[BK][BN];
    __shared__ int   gIdx[BM];

    const int tx  = threadIdx.x;            // 0..15
    const int ty  = threadIdx.y;            // 0..15
    const int tid = ty * 16 + tx;           // 0..255
    const int rowBase = blockIdx.y * BM;
    const int colBase = blockIdx.x * BN;

    if (GATHER) {
        for (int i = tid; i < BM; i += 256) gIdx[i] = gather[rowBase + i];
    }
    __syncthreads();

    constexpr int A_IT = (BM * BK) / (256 * 4);   // float4 loads per thread (A)
    constexpr int B_IT = (BN * BK) / (256 * 4);

    const int ldRow = tid / 4;          // 0..63 (stride 64 per iteration)
    const int k4    = (tid % 4) * 4;    // k offset within 16-wide k-tile

    float4 aReg[A_IT], bReg[B_IT];

    auto loadTile = [&](int k0) {
#pragma unroll
        for (int it = 0; it < A_IT; ++it) {
            int r = ldRow + it * 64;
            int gr = GATHER ? gIdx[r] : (rowBase + r);
            aReg[it] = *(const float4*)(A + (size_t)gr * K + k0 + k4);
        }
#pragma unroll
        for (int it = 0; it < B_IT; ++it) {
            int r = ldRow + it * 64;
            bReg[it] = *(const float4*)(W + (size_t)(colBase + r) * K + k0 + k4);
        }
    };
    auto storeTile = [&]() {
#pragma unroll
        for (int it = 0; it < A_IT; ++it) {
            int r = ldRow + it * 64;
            As[k4 + 0][r] = aReg[it].x;
            As[k4 + 1][r] = aReg[it].y;
            As[k4 + 2][r] = aReg[it].z;
            As[k4 + 3][r] = aReg[it].w;
        }
#pragma unroll
        for (int it = 0; it < B_IT; ++it) {
            int r = ldRow + it * 64;
            Bs[k4 + 0][r] = bReg[it].x;
            Bs[k4 + 1][r] = bReg[it].y;
            Bs[k4 + 2][r] = bReg[it].z;
            Bs[k4 + 3][r] = bReg[it].w;
        }
    };

    float acc[TM][TN];
#pragma unroll
    for (int i = 0; i < TM; ++i)
#pragma unroll
        for (int j = 0; j < TN; ++j) acc[i][j] = 0.f;

    const int numK = K / BK;
    loadTile(0);
    storeTile();
    __syncthreads();

    for (int kt = 0; kt < numK; ++kt) {
        if (kt + 1 < numK) loadTile((kt + 1) * BK);

        float ra[TM], rb[TN];
#pragma unroll
        for (int kk = 0; kk < BK; ++kk) {
#pragma unroll
            for (int i = 0; i < TM / 4; ++i)
                *(float4*)&ra[i * 4] = *(const float4*)&As[kk][ty * TM + i * 4];
#pragma unroll
            for (int j = 0; j < TN / 4; ++j)
                *(float4*)&rb[j * 4] = *(const float4*)&Bs[kk][tx * TN + j * 4];
#pragma unroll
            for (int i = 0; i < TM; ++i)
#pragma unroll
                for (int j = 0; j < TN; ++j)
                    acc[i][j] += ra[i] * rb[j];
        }
        __syncthreads();
        if (kt + 1 < numK) {
            storeTile();
            __syncthreads();
        }
    }

    // Epilogue
#pragma unroll
    for (int i = 0; i < TM; ++i) {
        const int m = rowBase + ty * TM + i;
#pragma unroll
        for (int j4 = 0; j4 < TN / 4; ++j4) {
            const int n0 = colBase + tx * TN + j4 * 4;
            float v[4];
#pragma unroll
            for (int c = 0; c < 4; ++c) {
                float x = acc[i][j4 * 4 + c] + bias[n0 + c];
                if (EPI >= 1) x = tanhf(x);
                if (EPI == 2) x *= mul[(size_t)m * N + n0 + c];
                v[c] = x;
            }
            float4 o; o.x = v[0]; o.y = v[1]; o.z = v[2]; o.w = v[3];
            *(float4*)(C + (size_t)m * N + n0) = o;
        }
    }
}

// ---------------------------------------------------------------------------
// Per-row minmax scale + L2 normalize: z = (z-min)/(max-min); z /= max(||z||,1e-12)
// One block (256 threads) per row of 768.
// ---------------------------------------------------------------------------
__global__ void rownorm_kernel(float* __restrict__ Z)
{
    __shared__ float shA[8], shB[8];
    const int t = threadIdx.x;
    float* z = Z + (size_t)blockIdx.x * DIN;

    float v0 = z[t], v1 = z[t + 256], v2 = z[t + 512];

    float mn = fminf(v0, fminf(v1, v2));
    float mx = fmaxf(v0, fmaxf(v1, v2));
#pragma unroll
    for (int o = 16; o > 0; o >>= 1) {
        mn = fminf(mn, __shfl_xor_sync(0xffffffffu, mn, o));
        mx = fmaxf(mx, __shfl_xor_sync(0xffffffffu, mx, o));
    }
    if ((t & 31) == 0) { shA[t >> 5] = mn; shB[t >> 5] = mx; }
    __syncthreads();
    float rmn = shA[0], rmx = shB[0];
#pragma unroll
    for (int i = 1; i < 8; ++i) { rmn = fminf(rmn, shA[i]); rmx = fmaxf(rmx, shB[i]); }

    const float sc = 1.f / (rmx - rmn);
    v0 = (v0 - rmn) * sc;
    v1 = (v1 - rmn) * sc;
    v2 = (v2 - rmn) * sc;

    float ss = v0 * v0 + v1 * v1 + v2 * v2;
#pragma unroll
    for (int o = 16; o > 0; o >>= 1)
        ss += __shfl_xor_sync(0xffffffffu, ss, o);
    __syncthreads();              // shA reuse hazard guard
    if ((t & 31) == 0) shA[t >> 5] = ss;
    __syncthreads();
    float tot = 0.f;
#pragma unroll
    for (int i = 0; i < 8; ++i) tot += shA[i];

    const float inv = 1.f / fmaxf(sqrtf(tot), 1e-12f);
    z[t]       = v0 * inv;
    z[t + 256] = v1 * inv;
    z[t + 512] = v2 * inv;
}

// ---------------------------------------------------------------------------
// o_f = h @ W_fc3^T + b_fc3   [8192, 50], K=256. Block handles 16 rows.
// ---------------------------------------------------------------------------
__global__ void fc3_kernel(const float* __restrict__ h,
                           const float* __restrict__ W,
                           const float* __restrict__ b,
                           float* __restrict__ out)
{
    __shared__ float hs[16 * HID];
    const int r0 = blockIdx.x * 16;
    for (int i = threadIdx.x; i < 16 * HID / 4; i += 256)
        ((float4*)hs)[i] = ((const float4*)(h + (size_t)r0 * HID))[i];
    __syncthreads();

    for (int o = threadIdx.x; o < 16 * OUTFE; o += 256) {
        const int r = o / OUTFE, c = o % OUTFE;
        const float* w = W + (size_t)c * HID;
        const float* hr = hs + r * HID;
        float acc = 0.f;
#pragma unroll 8
        for (int k = 0; k < HID; ++k) acc += hr[k] * w[k];
        out[(size_t)(r0 + r) * OUTFE + c] = acc + b[c];
    }
}

// ---------------------------------------------------------------------------
extern "C" void kernel_launch(void* const* d_in, const int* in_sizes, int n_in,
                              void* d_out, int out_size)
{
    const float* t_in   = (const float*)d_in[0];
    const float* AGE    = (const float*)d_in[1];
    const int*   Endx   = (const int*)  d_in[2];
    const float* W_age  = (const float*)d_in[3];
    const float* b_age  = (const float*)d_in[4];
    const float* W_prjT = (const float*)d_in[5];
    const float* b_prjT = (const float*)d_in[6];
    const float* W_prjL = (const float*)d_in[7];
    const float* b_prjL = (const float*)d_in[8];
    const float* outW   = (const float*)d_in[9];
    const float* outb   = (const float*)d_in[10];
    const float* W_fc3  = (const float*)d_in[11];
    const float* b_fc3  = (const float*)d_in[12];

    float* o_c = (float*)d_out;
    float* o_f = o_c + (size_t)NN * MM;

    float *Z, *EW, *h;
    cudaGetSymbolAddress((void**)&Z,  g_Z);
    cudaGetSymbolAddress((void**)&EW, g_EW);
    cudaGetSymbolAddress((void**)&h,  g_h);

    dim3 thr(16, 16);

    // 1) Z = AGE_inx[Endx] @ W_age^T + b_age   [4096, 768], K=768, gathered A
    sgemm_nt<128, 128, 8, 8, 0, true><<<dim3(DIN / 128, MM / 128), thr>>>(
        AGE, W_age, b_age, nullptr, Z, DIN, DIN, Endx);

    // 2) per-row minmax scale + L2 normalize (in place)
    rownorm_kernel<<<MM, 256>>>(Z);

    // 3) EW = tanh(Z @ W_prjL^T + b_prjL) * outW   [4096, 256], K=768
    sgemm_nt<64, 64, 4, 4, 2, false><<<dim3(HID / 64, MM / 64), thr>>>(
        Z, W_prjL, b_prjL, outW, EW, HID, DIN, nullptr);

    // 4) h = tanh(t @ W_prjT^T + b_prjT)   [8192, 256], K=768
    sgemm_nt<64, 64, 4, 4, 1, false><<<dim3(HID / 64, NN / 64), thr>>>(
        t_in, W_prjT, b_prjT, nullptr, h, HID, DIN, nullptr);

    // 5) o_c = h @ EW^T + outb   [8192, 4096], K=256
    sgemm_nt<128, 128, 8, 8, 0, false><<<dim3(MM / 128, NN / 128), thr>>>(
        h, EW, outb, nullptr, o_c, MM, HID, nullptr);

    // 6) o_f = h @ W_fc3^T + b_fc3   [8192, 50], K=256
    fc3_kernel<<<NN / 16, 256>>>(h, W_fc3, b_fc3, o_f);
}

// round 4
// speedup vs baseline: 1.2993x; 1.2993x over previous
#include <cuda_runtime.h>

#define DIN 768
#define HID 256
#define NN  8192
#define MM  4096
#define OUTFE 50

// Scratch (device globals: no allocations allowed)
__device__ float g_Z[(size_t)MM * DIN];    // gathered AGE rows -> lintrans output
__device__ float g_EW[(size_t)MM * HID];   // tanh(E) * outW
__device__ float g_h[(size_t)NN * HID];    // tanh(t @ W_prjT^T + b)

__device__ __forceinline__ unsigned f2tf(float x) {
    unsigned r;
    asm("cvt.rna.tf32.f32 %0, %1;" : "=r"(r) : "f"(x));
    return r;
}

__device__ __forceinline__ void mma_tf32(float* d, const unsigned* a, const unsigned* b) {
    asm volatile(
        "mma.sync.aligned.m16n8k8.row.col.f32.tf32.tf32.f32 "
        "{%0,%1,%2,%3}, {%4,%5,%6,%7}, {%8,%9}, {%0,%1,%2,%3};"
        : "+f"(d[0]), "+f"(d[1]), "+f"(d[2]), "+f"(d[3])
        : "r"(a[0]), "r"(a[1]), "r"(a[2]), "r"(a[3]), "r"(b[0]), "r"(b[1]));
}

// ---------------------------------------------------------------------------
// TF32 tensor-core GEMM:  C[m,n] = epi( sum_k A[row(m),k] * W[n,k] + bias[n] )
//   row(m) = gather ? gather[m] : m   (A row-major [*,K], W row-major [N,K])
//   EPI: 0 = none, 1 = tanh, 2 = tanh then * mul[m*N+n]
// 256 threads (8 warps). BK=32. Warp tile WM x WN of m16n8k8 MMAs.
// Smem k-major with +8 padding -> conflict-free fragment LDS.
// ---------------------------------------------------------------------------
template<int BM, int BN, int WM, int WN, int EPI, bool GATHER>
__global__ void __launch_bounds__(256, 1)
gemm_tf32(const float* __restrict__ A,
          const float* __restrict__ W,
          const float* __restrict__ bias,
          const float* __restrict__ mul,
          float* __restrict__ C,
          int N, int K,
          const int* __restrict__ gather)
{
    constexpr int BK  = 32;
    constexpr int MW  = BM / WM;       // warps along M
    constexpr int MT  = WM / 16;       // mma tiles per warp (M)
    constexpr int NT  = WN / 8;        // mma tiles per warp (N)
    constexpr int LDA = BM + 8;        // LDA % 32 == 8 -> conflict-free frags
    constexpr int LDB = BN + 8;
    constexpr int AIT = BM / 32;       // float4 ldg iterations per thread (A)
    constexpr int BIT = BN / 32;

    __shared__ unsigned As[BK * LDA];
    __shared__ unsigned Bs[BK * LDB];
    __shared__ int gIdx[BM];

    const int tid   = threadIdx.x;
    const int lane  = tid & 31;
    const int warp  = tid >> 5;
    const int warpM = warp % MW;
    const int warpN = warp / MW;
    const int rowBase = blockIdx.y * BM;
    const int colBase = blockIdx.x * BN;

    if (GATHER) {
        for (int i = tid; i < BM; i += 256) gIdx[i] = gather[rowBase + i];
        __syncthreads();
    }

    const int k4 = warp * 4;   // this warp's k-offset for float4 loads
    float4 aR[AIT], bR[BIT];

    auto ldg = [&](int k0) {
#pragma unroll
        for (int i = 0; i < AIT; ++i) {
            int m = lane + i * 32;
            int gr = GATHER ? gIdx[m] : (rowBase + m);
            aR[i] = *(const float4*)(A + (size_t)gr * K + k0 + k4);
        }
#pragma unroll
        for (int i = 0; i < BIT; ++i) {
            int n = lane + i * 32;
            bR[i] = *(const float4*)(W + (size_t)(colBase + n) * K + k0 + k4);
        }
    };
    auto sts = [&]() {
#pragma unroll
        for (int i = 0; i < AIT; ++i) {
            int m = lane + i * 32;
            As[(k4 + 0) * LDA + m] = f2tf(aR[i].x);
            As[(k4 + 1) * LDA + m] = f2tf(aR[i].y);
            As[(k4 + 2) * LDA + m] = f2tf(aR[i].z);
            As[(k4 + 3) * LDA + m] = f2tf(aR[i].w);
        }
#pragma unroll
        for (int i = 0; i < BIT; ++i) {
            int n = lane + i * 32;
            Bs[(k4 + 0) * LDB + n] = f2tf(bR[i].x);
            Bs[(k4 + 1) * LDB + n] = f2tf(bR[i].y);
            Bs[(k4 + 2) * LDB + n] = f2tf(bR[i].z);
            Bs[(k4 + 3) * LDB + n] = f2tf(bR[i].w);
        }
    };

    float acc[MT][NT][4];
#pragma unroll
    for (int i = 0; i < MT; ++i)
#pragma unroll
        for (int j = 0; j < NT; ++j)
#pragma unroll
            for (int c = 0; c < 4; ++c) acc[i][j][c] = 0.f;

    const int nChunks = K / BK;
    ldg(0);
    sts();
    __syncthreads();

    const int fr = lane >> 2;   // fragment row (0..7)
    const int fc = lane & 3;    // fragment k   (0..3)

    for (int kc = 0; kc < nChunks; ++kc) {
        if (kc + 1 < nChunks) ldg((kc + 1) * BK);

#pragma unroll
        for (int ks = 0; ks < 4; ++ks) {
            const int kk = ks * 8;
            unsigned af[MT][4], bf[NT][2];
#pragma unroll
            for (int mt = 0; mt < MT; ++mt) {
                int m = warpM * WM + mt * 16 + fr;
                af[mt][0] = As[(kk + fc) * LDA + m];
                af[mt][1] = As[(kk + fc) * LDA + m + 8];
                af[mt][2] = As[(kk + fc + 4) * LDA + m];
                af[mt][3] = As[(kk + fc + 4) * LDA + m + 8];
            }
#pragma unroll
            for (int nt = 0; nt < NT; ++nt) {
                int n = warpN * WN + nt * 8 + fr;
                bf[nt][0] = Bs[(kk + fc) * LDB + n];
                bf[nt][1] = Bs[(kk + fc + 4) * LDB + n];
            }
#pragma unroll
            for (int mt = 0; mt < MT; ++mt)
#pragma unroll
                for (int nt = 0; nt < NT; ++nt)
                    mma_tf32(acc[mt][nt], af[mt], bf[nt]);
        }
        __syncthreads();
        if (kc + 1 < nChunks) {
            sts();
            __syncthreads();
        }
    }

    // Epilogue: c0,c1 at (r, 2c), (r, 2c+1); c2,c3 at (r+8, 2c), (r+8, 2c+1)
#pragma unroll
    for (int mt = 0; mt < MT; ++mt) {
        const int m = rowBase + warpM * WM + mt * 16 + fr;
#pragma unroll
        for (int nt = 0; nt < NT; ++nt) {
            const int n = colBase + warpN * WN + nt * 8 + 2 * fc;
            const float bn0 = bias[n], bn1 = bias[n + 1];
            float v0 = acc[mt][nt][0] + bn0;
            float v1 = acc[mt][nt][1] + bn1;
            float v2 = acc[mt][nt][2] + bn0;
            float v3 = acc[mt][nt][3] + bn1;
            if (EPI >= 1) {
                v0 = tanhf(v0); v1 = tanhf(v1);
                v2 = tanhf(v2); v3 = tanhf(v3);
            }
            if (EPI == 2) {
                v0 *= mul[(size_t)m * N + n];
                v1 *= mul[(size_t)m * N + n + 1];
                v2 *= mul[(size_t)(m + 8) * N + n];
                v3 *= mul[(size_t)(m + 8) * N + n + 1];
            }
            float2 lo; lo.x = v0; lo.y = v1;
            float2 hi; hi.x = v2; hi.y = v3;
            *(float2*)(C + (size_t)m * N + n)       = lo;
            *(float2*)(C + (size_t)(m + 8) * N + n) = hi;
        }
    }
}

// ---------------------------------------------------------------------------
// Per-row minmax scale + L2 normalize: z = (z-min)/(max-min); z /= max(||z||,1e-12)
// One block (256 threads) per row of 768.
// ---------------------------------------------------------------------------
__global__ void rownorm_kernel(float* __restrict__ Z)
{
    __shared__ float shA[8], shB[8];
    const int t = threadIdx.x;
    float* z = Z + (size_t)blockIdx.x * DIN;

    float v0 = z[t], v1 = z[t + 256], v2 = z[t + 512];

    float mn = fminf(v0, fminf(v1, v2));
    float mx = fmaxf(v0, fmaxf(v1, v2));
#pragma unroll
    for (int o = 16; o > 0; o >>= 1) {
        mn = fminf(mn, __shfl_xor_sync(0xffffffffu, mn, o));
        mx = fmaxf(mx, __shfl_xor_sync(0xffffffffu, mx, o));
    }
    if ((t & 31) == 0) { shA[t >> 5] = mn; shB[t >> 5] = mx; }
    __syncthreads();
    float rmn = shA[0], rmx = shB[0];
#pragma unroll
    for (int i = 1; i < 8; ++i) { rmn = fminf(rmn, shA[i]); rmx = fmaxf(rmx, shB[i]); }

    const float sc = 1.f / (rmx - rmn);
    v0 = (v0 - rmn) * sc;
    v1 = (v1 - rmn) * sc;
    v2 = (v2 - rmn) * sc;

    float ss = v0 * v0 + v1 * v1 + v2 * v2;
#pragma unroll
    for (int o = 16; o > 0; o >>= 1)
        ss += __shfl_xor_sync(0xffffffffu, ss, o);
    __syncthreads();
    if ((t & 31) == 0) shA[t >> 5] = ss;
    __syncthreads();
    float tot = 0.f;
#pragma unroll
    for (int i = 0; i < 8; ++i) tot += shA[i];

    const float inv = 1.f / fmaxf(sqrtf(tot), 1e-12f);
    z[t]       = v0 * inv;
    z[t + 256] = v1 * inv;
    z[t + 512] = v2 * inv;
}

// ---------------------------------------------------------------------------
// o_f = h @ W_fc3^T + b_fc3   [8192, 50], K=256. Block handles 16 rows.
// ---------------------------------------------------------------------------
__global__ void fc3_kernel(const float* __restrict__ h,
                           const float* __restrict__ W,
                           const float* __restrict__ b,
                           float* __restrict__ out)
{
    __shared__ float hs[16 * HID];
    const int r0 = blockIdx.x * 16;
    for (int i = threadIdx.x; i < 16 * HID / 4; i += 256)
        ((float4*)hs)[i] = ((const float4*)(h + (size_t)r0 * HID))[i];
    __syncthreads();

    for (int o = threadIdx.x; o < 16 * OUTFE; o += 256) {
        const int r = o / OUTFE, c = o % OUTFE;
        const float* w = W + (size_t)c * HID;
        const float* hr = hs + r * HID;
        float acc = 0.f;
#pragma unroll 8
        for (int k = 0; k < HID; ++k) acc += hr[k] * w[k];
        out[(size_t)(r0 + r) * OUTFE + c] = acc + b[c];
    }
}

// ---------------------------------------------------------------------------
extern "C" void kernel_launch(void* const* d_in, const int* in_sizes, int n_in,
                              void* d_out, int out_size)
{
    const float* t_in   = (const float*)d_in[0];
    const float* AGE    = (const float*)d_in[1];
    const int*   Endx   = (const int*)  d_in[2];
    const float* W_age  = (const float*)d_in[3];
    const float* b_age  = (const float*)d_in[4];
    const float* W_prjT = (const float*)d_in[5];
    const float* b_prjT = (const float*)d_in[6];
    const float* W_prjL = (const float*)d_in[7];
    const float* b_prjL = (const float*)d_in[8];
    const float* outW   = (const float*)d_in[9];
    const float* outb   = (const float*)d_in[10];
    const float* W_fc3  = (const float*)d_in[11];
    const float* b_fc3  = (const float*)d_in[12];

    float* o_c = (float*)d_out;
    float* o_f = o_c + (size_t)NN * MM;

    float *Z, *EW, *h;
    cudaGetSymbolAddress((void**)&Z,  g_Z);
    cudaGetSymbolAddress((void**)&EW, g_EW);
    cudaGetSymbolAddress((void**)&h,  g_h);

    // 1) Z = AGE_inx[Endx] @ W_age^T + b_age   [4096, 768], K=768, gathered A
    gemm_tf32<128, 128, 32, 64, 0, true><<<dim3(DIN / 128, MM / 128), 256>>>(
        AGE, W_age, b_age, nullptr, Z, DIN, DIN, Endx);

    // 2) per-row minmax scale + L2 normalize (in place)
    rownorm_kernel<<<MM, 256>>>(Z);

    // 3) EW = tanh(Z @ W_prjL^T + b_prjL) * outW   [4096, 256], K=768
    gemm_tf32<64, 128, 32, 32, 2, false><<<dim3(HID / 128, MM / 64), 256>>>(
        Z, W_prjL, b_prjL, outW, EW, HID, DIN, nullptr);

    // 4) h = tanh(t @ W_prjT^T + b_prjT)   [8192, 256], K=768
    gemm_tf32<64, 128, 32, 32, 1, false><<<dim3(HID / 128, NN / 64), 256>>>(
        t_in, W_prjT, b_prjT, nullptr, h, HID, DIN, nullptr);

    // 5) o_c = h @ EW^T + outb   [8192, 4096], K=256
    gemm_tf32<128, 128, 32, 64, 0, false><<<dim3(MM / 128, NN / 128), 256>>>(
        h, EW, outb, nullptr, o_c, MM, HID, nullptr);

    // 6) o_f = h @ W_fc3^T + b_fc3   [8192, 50], K=256
    fc3_kernel<<<NN / 16, 256>>>(h, W_fc3, b_fc3, o_f);
}

// round 6
// speedup vs baseline: 1.8497x; 1.4236x over previous
#include <cuda_runtime.h>

#define DIN 768
#define HID 256
#define NN  8192
#define MM  4096
#define OUTFE 50

// Scratch (device globals: no allocations allowed)
__device__ float g_Z [(size_t)MM * DIN];   // lintrans output (tf32-rounded by rownorm)
__device__ float g_EW[(size_t)MM * HID];   // tanh(E) * outW (tf32-rounded)
__device__ float g_h [(size_t)NN * HID];   // tanh(t @ W_prjT^T + b) (tf32-rounded)
__device__ float g_t [(size_t)NN * DIN];   // tf32-rounded t
__device__ float g_Ag[(size_t)MM * DIN];   // tf32-rounded gathered AGE rows
__device__ float g_Wa[(size_t)DIN * DIN];  // tf32-rounded W_age
__device__ float g_Wt[(size_t)HID * DIN];  // tf32-rounded W_prjT
__device__ float g_Wl[(size_t)HID * DIN];  // tf32-rounded W_prjL

__device__ __forceinline__ unsigned f2tf(float x) {
    unsigned r;
    asm("cvt.rna.tf32.f32 %0, %1;" : "=r"(r) : "f"(x));
    return r;
}
__device__ __forceinline__ float rndtf(float x) { return __uint_as_float(f2tf(x)); }

__device__ __forceinline__ void mma_tf32(float* d, const unsigned* a, const unsigned* b) {
    asm volatile(
        "mma.sync.aligned.m16n8k8.row.col.f32.tf32.tf32.f32 "
        "{%0,%1,%2,%3}, {%4,%5,%6,%7}, {%8,%9}, {%0,%1,%2,%3};"
        : "+f"(d[0]), "+f"(d[1]), "+f"(d[2]), "+f"(d[3])
        : "r"(a[0]), "r"(a[1]), "r"(a[2]), "r"(a[3]), "r"(b[0]), "r"(b[1]));
}

__device__ __forceinline__ void cpasync16(unsigned d, const void* g) {
    asm volatile("cp.async.cg.shared.global [%0], [%1], 16;" :: "r"(d), "l"(g));
}
__device__ __forceinline__ void cp_commit() {
    asm volatile("cp.async.commit_group;");
}
__device__ __forceinline__ void cp_wait1() {
    asm volatile("cp.async.wait_group 1;");
}

// ---------------------------------------------------------------------------
// tf32-round elementwise copy (float4 vectorized)
// ---------------------------------------------------------------------------
__global__ void round4_kernel(const float4* __restrict__ in, float4* __restrict__ out, int n4)
{
    int i = blockIdx.x * blockDim.x + threadIdx.x;
    if (i < n4) {
        float4 v = in[i];
        v.x = rndtf(v.x); v.y = rndtf(v.y); v.z = rndtf(v.z); v.w = rndtf(v.w);
        out[i] = v;
    }
}

// gather AGE rows via Endx + tf32 round.  grid=M, block=192 (192*4 = 768 cols)
__global__ void gather_round_kernel(const float* __restrict__ AGE,
                                    const int* __restrict__ idx,
                                    float* __restrict__ out)
{
    const int m = blockIdx.x;
    const int r = idx[m];
    float4 v = ((const float4*)(AGE + (size_t)r * DIN))[threadIdx.x];
    v.x = rndtf(v.x); v.y = rndtf(v.y); v.z = rndtf(v.z); v.w = rndtf(v.w);
    ((float4*)(out + (size_t)m * DIN))[threadIdx.x] = v;
}

// ---------------------------------------------------------------------------
// TF32 tensor-core GEMM, 3-stage cp.async pipeline, XOR-swizzled smem.
//   C[m,n] = epi( sum_k A[m,k]*W[n,k] + bias[n] )
//   A row-major [M,K] (pre-rounded tf32 bits), W row-major [N,K] (pre-rounded)
//   EPI: 0 = none; 1 = tanh (round output); 2 = tanh * mul[m*N+n] (round output)
// BN=128, BK=32, 256 threads. BM=128: warp tile 32x64; BM=64: warp tile 32x32.
// ---------------------------------------------------------------------------
template<int BM, int EPI>
__global__ void __launch_bounds__(256, 2)
gemm_tc(const float* __restrict__ A, const float* __restrict__ W,
        const float* __restrict__ bias, const float* __restrict__ mul,
        float* __restrict__ C, int N, int K)
{
    constexpr int BN = 128, BK = 32, S = 3;
    constexpr int MW    = BM / 32;        // warps along M
    constexpr int NWARP = 8 / MW;         // warps along N
    constexpr int WN    = BN / NWARP;     // 64 (BM=128) or 32 (BM=64)
    constexpr int NT    = WN / 8;
    constexpr int ASZ = BM * BK, BSZ = BN * BK;

    extern __shared__ unsigned smem[];
    unsigned* As = smem;
    unsigned* Bs = smem + S * ASZ;

    const int tid  = threadIdx.x;
    const int lane = tid & 31;
    const int warp = tid >> 5;
    const int warpM = warp % MW;
    const int warpN = warp / MW;
    const int rowBase = blockIdx.y * BM;
    const int colBase = blockIdx.x * BN;
    const int lr = tid >> 3;   // 0..31: row within a 32-row load pass
    const int lc = tid & 7;    // float4 column 0..7

    const unsigned aSm = (unsigned)__cvta_generic_to_shared(As);
    const unsigned bSm = (unsigned)__cvta_generic_to_shared(Bs);

    auto ldgsts = [&](int stage, int k0) {
#pragma unroll
        for (int p = 0; p < BM / 32; ++p) {
            const int m = lr + p * 32;
            unsigned d = aSm + (unsigned)((stage * ASZ + m * 32 + ((lc ^ (m & 7)) << 2)) * 4);
            cpasync16(d, A + (size_t)(rowBase + m) * K + k0 + lc * 4);
        }
#pragma unroll
        for (int p = 0; p < 4; ++p) {
            const int n = lr + p * 32;
            unsigned d = bSm + (unsigned)((stage * BSZ + n * 32 + ((lc ^ (n & 7)) << 2)) * 4);
            cpasync16(d, W + (size_t)(colBase + n) * K + k0 + lc * 4);
        }
    };

    float acc[2][NT][4];
#pragma unroll
    for (int i = 0; i < 2; ++i)
#pragma unroll
        for (int j = 0; j < NT; ++j)
#pragma unroll
            for (int c = 0; c < 4; ++c) acc[i][j][c] = 0.f;

    const int nCh = K / BK;
    ldgsts(0, 0);   cp_commit();
    ldgsts(1, BK);  cp_commit();

    const int fr = lane >> 2;   // 0..7
    const int fc = lane & 3;    // 0..3

    for (int kc = 0; kc < nCh; ++kc) {
        cp_wait1();
        __syncthreads();
        const int nx = kc + 2;
        if (nx < nCh) ldgsts(nx % S, nx * BK);
        cp_commit();

        const unsigned* as = As + (kc % S) * ASZ;
        const unsigned* bs = Bs + (kc % S) * BSZ;

#pragma unroll
        for (int ks = 0; ks < 4; ++ks) {
            const int g0 = 2 * ks;       // float4-group of k = ks*8 + fc
            const int g1 = 2 * ks + 1;   // float4-group of k = ks*8 + fc + 4
            unsigned af[2][4], bf[NT][2];
#pragma unroll
            for (int mt = 0; mt < 2; ++mt) {
                const int m  = warpM * 32 + mt * 16 + fr;
                const int m7 = m & 7;
                af[mt][0] = as[m * 32 + ((g0 ^ m7) << 2) + fc];
                af[mt][1] = as[(m + 8) * 32 + ((g0 ^ m7) << 2) + fc];
                af[mt][2] = as[m * 32 + ((g1 ^ m7) << 2) + fc];
                af[mt][3] = as[(m + 8) * 32 + ((g1 ^ m7) << 2) + fc];
            }
#pragma unroll
            for (int nt = 0; nt < NT; ++nt) {
                const int n  = warpN * WN + nt * 8 + fr;
                const int n7 = n & 7;
                bf[nt][0] = bs[n * 32 + ((g0 ^ n7) << 2) + fc];
                bf[nt][1] = bs[n * 32 + ((g1 ^ n7) << 2) + fc];
            }
#pragma unroll
            for (int mt = 0; mt < 2; ++mt)
#pragma unroll
                for (int nt = 0; nt < NT; ++nt)
                    mma_tf32(acc[mt][nt], af[mt], bf[nt]);
        }
    }

    // Epilogue: c0,c1 at (r, 2c),(r, 2c+1); c2,c3 at (r+8, 2c),(r+8, 2c+1)
#pragma unroll
    for (int mt = 0; mt < 2; ++mt) {
        const int m = rowBase + warpM * 32 + mt * 16 + fr;
#pragma unroll
        for (int nt = 0; nt < NT; ++nt) {
            const int n = colBase + warpN * WN + nt * 8 + 2 * fc;
            const float bn0 = bias[n], bn1 = bias[n + 1];
            float v0 = acc[mt][nt][0] + bn0;
            float v1 = acc[mt][nt][1] + bn1;
            float v2 = acc[mt][nt][2] + bn0;
            float v3 = acc[mt][nt][3] + bn1;
            if (EPI >= 1) {
                v0 = tanhf(v0); v1 = tanhf(v1);
                v2 = tanhf(v2); v3 = tanhf(v3);
            }
            if (EPI == 2) {
                v0 *= mul[(size_t)m * N + n];
                v1 *= mul[(size_t)m * N + n + 1];
                v2 *= mul[(size_t)(m + 8) * N + n];
                v3 *= mul[(size_t)(m + 8) * N + n + 1];
            }
            if (EPI >= 1) {   // outputs feed later tf32 GEMMs: round at write
                v0 = rndtf(v0); v1 = rndtf(v1);
                v2 = rndtf(v2); v3 = rndtf(v3);
            }
            float2 lo; lo.x = v0; lo.y = v1;
            float2 hi; hi.x = v2; hi.y = v3;
            *(float2*)(C + (size_t)m * N + n)       = lo;
            *(float2*)(C + (size_t)(m + 8) * N + n) = hi;
        }
    }
}

// ---------------------------------------------------------------------------
// Per-row minmax scale + L2 normalize; writes tf32-rounded (feeds tf32 GEMM).
// One block (256 threads) per row of 768.
// ---------------------------------------------------------------------------
__global__ void rownorm_kernel(float* __restrict__ Z)
{
    __shared__ float shA[8], shB[8];
    const int t = threadIdx.x;
    float* z = Z + (size_t)blockIdx.x * DIN;

    float v0 = z[t], v1 = z[t + 256], v2 = z[t + 512];

    float mn = fminf(v0, fminf(v1, v2));
    float mx = fmaxf(v0, fmaxf(v1, v2));
#pragma unroll
    for (int o = 16; o > 0; o >>= 1) {
        mn = fminf(mn, __shfl_xor_sync(0xffffffffu, mn, o));
        mx = fmaxf(mx, __shfl_xor_sync(0xffffffffu, mx, o));
    }
    if ((t & 31) == 0) { shA[t >> 5] = mn; shB[t >> 5] = mx; }
    __syncthreads();
    float rmn = shA[0], rmx = shB[0];
#pragma unroll
    for (int i = 1; i < 8; ++i) { rmn = fminf(rmn, shA[i]); rmx = fmaxf(rmx, shB[i]); }

    const float sc = 1.f / (rmx - rmn);
    v0 = (v0 - rmn) * sc;
    v1 = (v1 - rmn) * sc;
    v2 = (v2 - rmn) * sc;

    float ss = v0 * v0 + v1 * v1 + v2 * v2;
#pragma unroll
    for (int o = 16; o > 0; o >>= 1)
        ss += __shfl_xor_sync(0xffffffffu, ss, o);
    __syncthreads();
    if ((t & 31) == 0) shA[t >> 5] = ss;
    __syncthreads();
    float tot = 0.f;
#pragma unroll
    for (int i = 0; i < 8; ++i) tot += shA[i];

    const float inv = 1.f / fmaxf(sqrtf(tot), 1e-12f);
    z[t]       = rndtf(v0 * inv);
    z[t + 256] = rndtf(v1 * inv);
    z[t + 512] = rndtf(v2 * inv);
}

// ---------------------------------------------------------------------------
// o_f = h @ W_fc3^T + b_fc3   [8192, 50], K=256. Block handles 16 rows.
// ---------------------------------------------------------------------------
__global__ void fc3_kernel(const float* __restrict__ h,
                           const float* __restrict__ W,
                           const float* __restrict__ b,
                           float* __restrict__ out)
{
    __shared__ float hs[16 * HID];
    const int r0 = blockIdx.x * 16;
    for (int i = threadIdx.x; i < 16 * HID / 4; i += 256)
        ((float4*)hs)[i] = ((const float4*)(h + (size_t)r0 * HID))[i];
    __syncthreads();

    for (int o = threadIdx.x; o < 16 * OUTFE; o += 256) {
        const int r = o / OUTFE, c = o % OUTFE;
        const float* w = W + (size_t)c * HID;
        const float* hr = hs + r * HID;
        float acc = 0.f;
#pragma unroll 8
        for (int k = 0; k < HID; ++k) acc += hr[k] * w[k];
        out[(size_t)(r0 + r) * OUTFE + c] = acc + b[c];
    }
}

// ---------------------------------------------------------------------------
extern "C" void kernel_launch(void* const* d_in, const int* in_sizes, int n_in,
                              void* d_out, int out_size)
{
    const float* t_in   = (const float*)d_in[0];
    const float* AGE    = (const float*)d_in[1];
    const int*   Endx   = (const int*)  d_in[2];
    const float* W_age  = (const float*)d_in[3];
    const float* b_age  = (const float*)d_in[4];
    const float* W_prjT = (const float*)d_in[5];
    const float* b_prjT = (const float*)d_in[6];
    const float* W_prjL = (const float*)d_in[7];
    const float* b_prjL = (const float*)d_in[8];
    const float* outW   = (const float*)d_in[9];
    const float* outb   = (const float*)d_in[10];
    const float* W_fc3  = (const float*)d_in[11];
    const float* b_fc3  = (const float*)d_in[12];

    float* o_c = (float*)d_out;
    float* o_f = o_c + (size_t)NN * MM;

    float *Z, *EW, *h, *tT, *Ag, *Wa, *Wt, *Wl;
    cudaGetSymbolAddress((void**)&Z,  g_Z);
    cudaGetSymbolAddress((void**)&EW, g_EW);
    cudaGetSymbolAddress((void**)&h,  g_h);
    cudaGetSymbolAddress((void**)&tT, g_t);
    cudaGetSymbolAddress((void**)&Ag, g_Ag);
    cudaGetSymbolAddress((void**)&Wa, g_Wa);
    cudaGetSymbolAddress((void**)&Wt, g_Wt);
    cudaGetSymbolAddress((void**)&Wl, g_Wl);

    constexpr int SM128 = 3 * (128 + 128) * 32 * 4;   // 98304
    constexpr int SM64  = 3 * (64 + 128) * 32 * 4;    // 73728
    cudaFuncSetAttribute(gemm_tc<128, 0>, cudaFuncAttributeMaxDynamicSharedMemorySize, SM128);
    cudaFuncSetAttribute(gemm_tc<64, 1>,  cudaFuncAttributeMaxDynamicSharedMemorySize, SM64);
    cudaFuncSetAttribute(gemm_tc<64, 2>,  cudaFuncAttributeMaxDynamicSharedMemorySize, SM64);

    // 0) tf32 pre-rounding of GEMM operands
    {
        int n4 = NN * DIN / 4;
        round4_kernel<<<(n4 + 255) / 256, 256>>>((const float4*)t_in, (float4*)tT, n4);
        n4 = DIN * DIN / 4;
        round4_kernel<<<(n4 + 255) / 256, 256>>>((const float4*)W_age, (float4*)Wa, n4);
        n4 = HID * DIN / 4;
        round4_kernel<<<(n4 + 255) / 256, 256>>>((const float4*)W_prjT, (float4*)Wt, n4);
        round4_kernel<<<(n4 + 255) / 256, 256>>>((const float4*)W_prjL, (float4*)Wl, n4);
        gather_round_kernel<<<MM, 192>>>(AGE, Endx, Ag);
    }

    // 1) Z = Ag @ Wa^T + b_age   [4096, 768], K=768
    gemm_tc<128, 0><<<dim3(DIN / 128, MM / 128), 256, SM128>>>(Ag, Wa, b_age, nullptr, Z, DIN, DIN);

    // 2) per-row minmax scale + L2 normalize (in place, tf32-rounded out)
    rownorm_kernel<<<MM, 256>>>(Z);

    // 3) EW = tanh(Z @ Wl^T + b_prjL) * outW   [4096, 256], K=768
    gemm_tc<64, 2><<<dim3(HID / 128, MM / 64), 256, SM64>>>(Z, Wl, b_prjL, outW, EW, HID, DIN);

    // 4) h = tanh(tT @ Wt^T + b_prjT)   [8192, 256], K=768
    gemm_tc<64, 1><<<dim3(HID / 128, NN / 64), 256, SM64>>>(tT, Wt, b_prjT, nullptr, h, HID, DIN);

    // 5) o_c = h @ EW^T + outb   [8192, 4096], K=256
    gemm_tc<128, 0><<<dim3(MM / 128, NN / 128), 256, SM128>>>(h, EW, outb, nullptr, o_c, MM, HID);

    // 6) o_f = h @ W_fc3^T + b_fc3   [8192, 50], K=256
    fc3_kernel<<<NN / 16, 256>>>(h, W_fc3, b_fc3, o_f);
}

// round 9
// speedup vs baseline: 2.1329x; 1.1531x over previous
#include <cuda_runtime.h>
#include <cuda_fp16.h>
#include <cstdint>

#define DIN 768
#define HID 256
#define NN  8192
#define MM  4096
#define OUTFE 50

// Scratch (device globals: no allocations allowed)
__device__ __align__(256) float  g_Z  [(size_t)MM * DIN];  // gemm1 out (fp32)
__device__ __align__(256) __half g_Zh [(size_t)MM * DIN];  // rownorm out (fp16)
__device__ __align__(256) __half g_EW [(size_t)MM * HID];  // tanh(E)*outW (fp16)
__device__ __align__(256) __half g_h  [(size_t)NN * HID];  // tanh(t@WprjT^T+b) (fp16)
__device__ __align__(256) __half g_t  [(size_t)NN * DIN];  // fp16 t
__device__ __align__(256) __half g_Ag [(size_t)MM * DIN];  // fp16 gathered AGE rows
__device__ __align__(256) __half g_Wa [(size_t)DIN * DIN]; // fp16 W_age
__device__ __align__(256) __half g_Wt [(size_t)HID * DIN]; // fp16 W_prjT
__device__ __align__(256) __half g_Wl [(size_t)HID * DIN]; // fp16 W_prjL

__device__ __forceinline__ void cpasync16(uint32_t d, const void* g) {
    asm volatile("cp.async.cg.shared.global [%0], [%1], 16;" :: "r"(d), "l"(g));
}
__device__ __forceinline__ void cp_commit() { asm volatile("cp.async.commit_group;"); }
__device__ __forceinline__ void cp_wait1()  { asm volatile("cp.async.wait_group 1;"); }
__device__ __forceinline__ void cp_wait0()  { asm volatile("cp.async.wait_group 0;"); }

__device__ __forceinline__ void ldsm4(uint32_t& r0, uint32_t& r1, uint32_t& r2, uint32_t& r3,
                                      uint32_t addr) {
    asm volatile("ldmatrix.sync.aligned.m8n8.x4.shared.b16 {%0,%1,%2,%3}, [%4];"
                 : "=r"(r0), "=r"(r1), "=r"(r2), "=r"(r3) : "r"(addr));
}

__device__ __forceinline__ void mma_f16(float* d, const uint32_t* a, const uint32_t* b) {
    asm volatile(
        "mma.sync.aligned.m16n8k16.row.col.f32.f16.f16.f32 "
        "{%0,%1,%2,%3}, {%4,%5,%6,%7}, {%8,%9}, {%0,%1,%2,%3};"
        : "+f"(d[0]), "+f"(d[1]), "+f"(d[2]), "+f"(d[3])
        : "r"(a[0]), "r"(a[1]), "r"(a[2]), "r"(a[3]), "r"(b[0]), "r"(b[1]));
}

// ---------------------------------------------------------------------------
// fp16 tensor-core GEMM (mma.sync m16n8k16 + ldmatrix), 3-stage cp.async.
//   C[m,n] = epi( sum_k A[m,k]*W[n,k] + bias[n] )
//   A row-major [M,K] fp16, W row-major [N,K] fp16 (W row n == col n of B^T).
//   EPI: 0 = none, fp32 out; 1 = tanh, fp16 out; 2 = tanh*mul[m*N+n], fp16 out
// BM=BN=128, BK=64 (rows of 64 halfs = 128B, XOR-16B swizzle). 256 threads,
// 8 warps as 4(M)x2(N), warp tile 32x64 (MT=2 m16 tiles, NT=8 n8 tiles).
// ---------------------------------------------------------------------------
template<int EPI>
__global__ void __launch_bounds__(256, 2)
gemm_h(const __half* __restrict__ A, const __half* __restrict__ W,
       const float* __restrict__ bias, const float* __restrict__ mul,
       void* __restrict__ Cv, int N, int K)
{
    constexpr int BM = 128, BN = 128, BK = 64, S = 3;
    constexpr int TSZ = BM * BK * 2;          // 16 KB per operand tile
    constexpr int STG = 2 * TSZ;              // 32 KB per stage

    extern __shared__ char dyn[];
    const uint32_t dynB = (uint32_t)__cvta_generic_to_shared(dyn);
    const uint32_t base = (dynB + 1023u) & ~1023u;

    const int tid  = threadIdx.x;
    const int lane = tid & 31;
    const int warp = tid >> 5;
    const int warpM = warp & 3;
    const int warpN = warp >> 2;
    const int rowBase = blockIdx.y * BM;
    const int colBase = blockIdx.x * BN;

    // cp.async mapping: 1024 16B items per tile; item i -> row i>>3, chunk i&7
    auto ldchunk = [&](int stage, int k0) {
        const uint32_t aB = base + stage * STG;
        const uint32_t bB = aB + TSZ;
#pragma unroll
        for (int p = 0; p < 4; ++p) {
            const int i = tid + 256 * p;
            const int r = i >> 3, c = i & 7;
            cpasync16(aB + r * 128 + ((c ^ (r & 7)) << 4),
                      A + (size_t)(rowBase + r) * K + k0 + c * 8);
        }
#pragma unroll
        for (int p = 0; p < 4; ++p) {
            const int i = tid + 256 * p;
            const int r = i >> 3, c = i & 7;
            cpasync16(bB + r * 128 + ((c ^ (r & 7)) << 4),
                      W + (size_t)(colBase + r) * K + k0 + c * 8);
        }
        cp_commit();
    };

    float acc[2][8][4];
#pragma unroll
    for (int i = 0; i < 2; ++i)
#pragma unroll
        for (int j = 0; j < 8; ++j)
#pragma unroll
            for (int c = 0; c < 4; ++c) acc[i][j][c] = 0.f;

    const int nCh = K / BK;
    ldchunk(0, 0);
    ldchunk(1, BK);

    // ldmatrix lane geometry
    const int arow = warpM * 32 + (lane & 15);               // + mt*16
    const int achk = lane >> 4;                              // + 2*ks
    const int brow = warpN * 64 + (lane & 7) + ((lane >> 1) & 8);  // + p*16
    const int bchk = (lane >> 3) & 1;                        // + 2*ks

    for (int kc = 0; kc < nCh; ++kc) {
        if (kc == nCh - 1) cp_wait0(); else cp_wait1();
        __syncthreads();
        if (kc + 2 < nCh) ldchunk((kc + 2) % S, (kc + 2) * BK);

        const uint32_t aB = base + (kc % S) * STG;
        const uint32_t bB = aB + TSZ;

#pragma unroll
        for (int ks = 0; ks < 4; ++ks) {
            uint32_t af[2][4], bf[8][2];
#pragma unroll
            for (int mt = 0; mt < 2; ++mt) {
                const int r = arow + mt * 16;
                const int c = 2 * ks + achk;
                ldsm4(af[mt][0], af[mt][1], af[mt][2], af[mt][3],
                      aB + r * 128 + ((c ^ (r & 7)) << 4));
            }
#pragma unroll
            for (int p = 0; p < 4; ++p) {
                const int r = brow + p * 16;
                const int c = 2 * ks + bchk;
                ldsm4(bf[2 * p][0], bf[2 * p][1], bf[2 * p + 1][0], bf[2 * p + 1][1],
                      bB + r * 128 + ((c ^ (r & 7)) << 4));
            }
#pragma unroll
            for (int mt = 0; mt < 2; ++mt)
#pragma unroll
                for (int nt = 0; nt < 8; ++nt)
                    mma_f16(acc[mt][nt], af[mt], bf[nt]);
        }
    }

    // Epilogue: c0,c1 -> (m, 2fc),(m, 2fc+1); c2,c3 -> (m+8, ...)
    const int fr = lane >> 2;
    const int fc = lane & 3;
#pragma unroll
    for (int mt = 0; mt < 2; ++mt) {
        const int m = rowBase + warpM * 32 + mt * 16 + fr;
#pragma unroll
        for (int nt = 0; nt < 8; ++nt) {
            const int n = colBase + warpN * 64 + nt * 8 + 2 * fc;
            const float bn0 = bias[n], bn1 = bias[n + 1];
            float v0 = acc[mt][nt][0] + bn0;
            float v1 = acc[mt][nt][1] + bn1;
            float v2 = acc[mt][nt][2] + bn0;
            float v3 = acc[mt][nt][3] + bn1;
            if (EPI >= 1) {
                v0 = tanhf(v0); v1 = tanhf(v1);
                v2 = tanhf(v2); v3 = tanhf(v3);
            }
            if (EPI == 2) {
                v0 *= mul[(size_t)m * N + n];
                v1 *= mul[(size_t)m * N + n + 1];
                v2 *= mul[(size_t)(m + 8) * N + n];
                v3 *= mul[(size_t)(m + 8) * N + n + 1];
            }
            if (EPI == 0) {
                float* C = (float*)Cv;
                float2 lo; lo.x = v0; lo.y = v1;
                float2 hi; hi.x = v2; hi.y = v3;
                *(float2*)(C + (size_t)m * N + n)       = lo;
                *(float2*)(C + (size_t)(m + 8) * N + n) = hi;
            } else {
                __half* C = (__half*)Cv;
                *(__half2*)(C + (size_t)m * N + n)       = __floats2half2_rn(v0, v1);
                *(__half2*)(C + (size_t)(m + 8) * N + n) = __floats2half2_rn(v2, v3);
            }
        }
    }
}

// ---------------------------------------------------------------------------
// fp32 -> fp16 elementwise copy (4 elems/thread)
// ---------------------------------------------------------------------------
__global__ void f2h_kernel(const float4* __restrict__ in, __half2* __restrict__ out, int n4)
{
    int i = blockIdx.x * blockDim.x + threadIdx.x;
    if (i < n4) {
        float4 v = in[i];
        out[2 * i]     = __floats2half2_rn(v.x, v.y);
        out[2 * i + 1] = __floats2half2_rn(v.z, v.w);
    }
}

// gather AGE rows via Endx + fp16 convert.  grid=M, block=192 (192*4 = 768)
__global__ void gather_h_kernel(const float* __restrict__ AGE,
                                const int* __restrict__ idx,
                                __half* __restrict__ out)
{
    const int m = blockIdx.x;
    const int r = idx[m];
    float4 v = ((const float4*)(AGE + (size_t)r * DIN))[threadIdx.x];
    __half2* o = (__half2*)(out + (size_t)m * DIN) + 2 * threadIdx.x;
    o[0] = __floats2half2_rn(v.x, v.y);
    o[1] = __floats2half2_rn(v.z, v.w);
}

// ---------------------------------------------------------------------------
// Per-row minmax scale + L2 normalize (fp32 in, fp16 out).
// One block (256 threads) per row of 768.
// ---------------------------------------------------------------------------
__global__ void rownorm_kernel(const float* __restrict__ Z, __half* __restrict__ Zh)
{
    __shared__ float shA[8], shB[8];
    const int t = threadIdx.x;
    const float* z = Z + (size_t)blockIdx.x * DIN;
    __half* zo = Zh + (size_t)blockIdx.x * DIN;

    float v0 = z[t], v1 = z[t + 256], v2 = z[t + 512];

    float mn = fminf(v0, fminf(v1, v2));
    float mx = fmaxf(v0, fmaxf(v1, v2));
#pragma unroll
    for (int o = 16; o > 0; o >>= 1) {
        mn = fminf(mn, __shfl_xor_sync(0xffffffffu, mn, o));
        mx = fmaxf(mx, __shfl_xor_sync(0xffffffffu, mx, o));
    }
    if ((t & 31) == 0) { shA[t >> 5] = mn; shB[t >> 5] = mx; }
    __syncthreads();
    float rmn = shA[0], rmx = shB[0];
#pragma unroll
    for (int i = 1; i < 8; ++i) { rmn = fminf(rmn, shA[i]); rmx = fmaxf(rmx, shB[i]); }

    const float sc = 1.f / (rmx - rmn);
    v0 = (v0 - rmn) * sc;
    v1 = (v1 - rmn) * sc;
    v2 = (v2 - rmn) * sc;

    float ss = v0 * v0 + v1 * v1 + v2 * v2;
#pragma unroll
    for (int o = 16; o > 0; o >>= 1)
        ss += __shfl_xor_sync(0xffffffffu, ss, o);
    __syncthreads();
    if ((t & 31) == 0) shA[t >> 5] = ss;
    __syncthreads();
    float tot = 0.f;
#pragma unroll
    for (int i = 0; i < 8; ++i) tot += shA[i];

    const float inv = 1.f / fmaxf(sqrtf(tot), 1e-12f);
    zo[t]       = __float2half(v0 * inv);
    zo[t + 256] = __float2half(v1 * inv);
    zo[t + 512] = __float2half(v2 * inv);
}

// ---------------------------------------------------------------------------
// o_f = h @ W_fc3^T + b_fc3   [8192, 50], K=256. Block handles 16 rows.
// h is fp16; W_fc3 fp32; fp32 accumulate.
// ---------------------------------------------------------------------------
__global__ void fc3_kernel(const __half* __restrict__ h,
                           const float* __restrict__ W,
                           const float* __restrict__ b,
                           float* __restrict__ out)
{
    __shared__ float hs[16 * HID];
    const int r0 = blockIdx.x * 16;
    for (int i = threadIdx.x; i < 16 * HID / 2; i += 256) {
        __half2 p = ((const __half2*)(h + (size_t)r0 * HID))[i];
        float2 f = __half22float2(p);
        hs[2 * i] = f.x; hs[2 * i + 1] = f.y;
    }
    __syncthreads();

    for (int o = threadIdx.x; o < 16 * OUTFE; o += 256) {
        const int r = o / OUTFE, c = o % OUTFE;
        const float* w = W + (size_t)c * HID;
        const float* hr = hs + r * HID;
        float acc = 0.f;
#pragma unroll 8
        for (int k = 0; k < HID; ++k) acc += hr[k] * w[k];
        out[(size_t)(r0 + r) * OUTFE + c] = acc + b[c];
    }
}

// ---------------------------------------------------------------------------
extern "C" void kernel_launch(void* const* d_in, const int* in_sizes, int n_in,
                              void* d_out, int out_size)
{
    const float* t_in   = (const float*)d_in[0];
    const float* AGE    = (const float*)d_in[1];
    const int*   Endx   = (const int*)  d_in[2];
    const float* W_age  = (const float*)d_in[3];
    const float* b_age  = (const float*)d_in[4];
    const float* W_prjT = (const float*)d_in[5];
    const float* b_prjT = (const float*)d_in[6];
    const float* W_prjL = (const float*)d_in[7];
    const float* b_prjL = (const float*)d_in[8];
    const float* outW   = (const float*)d_in[9];
    const float* outb   = (const float*)d_in[10];
    const float* W_fc3  = (const float*)d_in[11];
    const float* b_fc3  = (const float*)d_in[12];

    float* o_c = (float*)d_out;
    float* o_f = o_c + (size_t)NN * MM;

    float *Z;
    __half *Zh, *EW, *h, *tH, *Ag, *Wa, *Wt, *Wl;
    cudaGetSymbolAddress((void**)&Z,  g_Z);
    cudaGetSymbolAddress((void**)&Zh, g_Zh);
    cudaGetSymbolAddress((void**)&EW, g_EW);
    cudaGetSymbolAddress((void**)&h,  g_h);
    cudaGetSymbolAddress((void**)&tH, g_t);
    cudaGetSymbolAddress((void**)&Ag, g_Ag);
    cudaGetSymbolAddress((void**)&Wa, g_Wa);
    cudaGetSymbolAddress((void**)&Wt, g_Wt);
    cudaGetSymbolAddress((void**)&Wl, g_Wl);

    // dynamic smem: 3 stages * 32KB + 1KB alignment slack
    constexpr int SMEM = 3 * 32768 + 1024;   // 99328
    cudaFuncSetAttribute(gemm_h<0>, cudaFuncAttributeMaxDynamicSharedMemorySize, SMEM);
    cudaFuncSetAttribute(gemm_h<1>, cudaFuncAttributeMaxDynamicSharedMemorySize, SMEM);
    cudaFuncSetAttribute(gemm_h<2>, cudaFuncAttributeMaxDynamicSharedMemorySize, SMEM);

    // 0) fp16 conversion of GEMM operands
    {
        int n4 = NN * DIN / 4;
        f2h_kernel<<<(n4 + 255) / 256, 256>>>((const float4*)t_in, (__half2*)tH, n4);
        n4 = DIN * DIN / 4;
        f2h_kernel<<<(n4 + 255) / 256, 256>>>((const float4*)W_age, (__half2*)Wa, n4);
        n4 = HID * DIN / 4;
        f2h_kernel<<<(n4 + 255) / 256, 256>>>((const float4*)W_prjT, (__half2*)Wt, n4);
        f2h_kernel<<<(n4 + 255) / 256, 256>>>((const float4*)W_prjL, (__half2*)Wl, n4);
        gather_h_kernel<<<MM, 192>>>(AGE, Endx, Ag);
    }

    // 1) Z = Ag @ Wa^T + b_age   [4096, 768], K=768 (fp32 out)
    gemm_h<0><<<dim3(DIN / 128, MM / 128), 256, SMEM>>>(Ag, Wa, b_age, nullptr, Z, DIN, DIN);

    // 2) per-row minmax scale + L2 normalize -> fp16
    rownorm_kernel<<<MM, 256>>>(Z, Zh);

    // 3) EW = tanh(Zh @ Wl^T + b_prjL) * outW   [4096, 256], K=768 (fp16 out)
    gemm_h<2><<<dim3(HID / 128, MM / 128), 256, SMEM>>>(Zh, Wl, b_prjL, outW, EW, HID, DIN);

    // 4) h = tanh(tH @ Wt^T + b_prjT)   [8192, 256], K=768 (fp16 out)
    gemm_h<1><<<dim3(HID / 128, NN / 128), 256, SMEM>>>(tH, Wt, b_prjT, nullptr, h, HID, DIN);

    // 5) o_c = h @ EW^T + outb   [8192, 4096], K=256 (fp32 out)
    gemm_h<0><<<dim3(MM / 128, NN / 128), 256, SMEM>>>(h, EW, outb, nullptr, o_c, MM, HID);

    // 6) o_f = h @ W_fc3^T + b_fc3   [8192, 50], K=256
    fc3_kernel<<<NN / 16, 256>>>(h, W_fc3, b_fc3, o_f);
}

// round 10
// speedup vs baseline: 2.1731x; 1.0189x over previous
#include <cuda_runtime.h>
#include <cuda_fp16.h>
#include <cstdint>

#define DIN 768
#define HID 256
#define NN  8192
#define MM  4096
#define OUTFE 50

// Scratch (device globals: no allocations allowed)
__device__ __align__(256) float  g_Z  [(size_t)MM * DIN];  // gemm1 out (fp32)
__device__ __align__(256) __half g_Zh [(size_t)MM * DIN];  // rownorm out (fp16)
__device__ __align__(256) __half g_EW [(size_t)MM * HID];  // tanh(E)*outW (fp16)
__device__ __align__(256) __half g_h  [(size_t)NN * HID];  // tanh(t@WprjT^T+b) (fp16)
__device__ __align__(256) __half g_t  [(size_t)NN * DIN];  // fp16 t
__device__ __align__(256) __half g_Ag [(size_t)MM * DIN];  // fp16 gathered AGE rows
__device__ __align__(256) __half g_Wa [(size_t)DIN * DIN]; // fp16 W_age
__device__ __align__(256) __half g_Wt [(size_t)HID * DIN]; // fp16 W_prjT
__device__ __align__(256) __half g_Wl [(size_t)HID * DIN]; // fp16 W_prjL

__device__ __forceinline__ void cpasync16(uint32_t d, const void* g) {
    asm volatile("cp.async.cg.shared.global [%0], [%1], 16;" :: "r"(d), "l"(g));
}
__device__ __forceinline__ void cp_commit() { asm volatile("cp.async.commit_group;"); }
__device__ __forceinline__ void cp_wait1()  { asm volatile("cp.async.wait_group 1;"); }
__device__ __forceinline__ void cp_wait0()  { asm volatile("cp.async.wait_group 0;"); }

__device__ __forceinline__ void ldsm4(uint32_t& r0, uint32_t& r1, uint32_t& r2, uint32_t& r3,
                                      uint32_t addr) {
    asm volatile("ldmatrix.sync.aligned.m8n8.x4.shared.b16 {%0,%1,%2,%3}, [%4];"
                 : "=r"(r0), "=r"(r1), "=r"(r2), "=r"(r3) : "r"(addr));
}

__device__ __forceinline__ void mma_f16(float* d, const uint32_t* a, const uint32_t* b) {
    asm volatile(
        "mma.sync.aligned.m16n8k16.row.col.f32.f16.f16.f32 "
        "{%0,%1,%2,%3}, {%4,%5,%6,%7}, {%8,%9}, {%0,%1,%2,%3};"
        : "+f"(d[0]), "+f"(d[1]), "+f"(d[2]), "+f"(d[3])
        : "r"(a[0]), "r"(a[1]), "r"(a[2]), "r"(a[3]), "r"(b[0]), "r"(b[1]));
}

// ---------------------------------------------------------------------------
// fp16 tensor-core GEMM (mma.sync m16n8k16 + ldmatrix), 3-stage cp.async.
//   C[m,n] = epi( sum_k A[m,k]*W[n,k] + bias[n] )
//   A row-major [M,K] fp16, W row-major [N,K] fp16.
//   EPI: 0 = none, fp32 out; 1 = tanh, fp16 out; 2 = tanh*mul[m*N+n], fp16 out
// BN=128, BK=64 (128B rows, XOR-16B swizzle), 256 threads (8 warps).
// BM=128: warps 4(M)x2(N), warp tile 32x64 (NT=8), stage 32KB.
// BM=64 : warps 2(M)x4(N), warp tile 32x32 (NT=4), stage 24KB.
// ---------------------------------------------------------------------------
template<int BM, int EPI>
__global__ void __launch_bounds__(256, 2)
gemm_h(const __half* __restrict__ A, const __half* __restrict__ W,
       const float* __restrict__ bias, const float* __restrict__ mul,
       void* __restrict__ Cv, int N, int K)
{
    constexpr int BN = 128, BK = 64, S = 3;
    constexpr int MWARP = BM / 32;            // 4 or 2
    constexpr int NWARP = 8 / MWARP;          // 2 or 4
    constexpr int WN    = BN / NWARP;         // 64 or 32
    constexpr int NT    = WN / 8;             // 8 or 4
    constexpr int ASZ = BM * BK * 2;          // 16 or 8 KB
    constexpr int BSZ = BN * BK * 2;          // 16 KB
    constexpr int STG = ASZ + BSZ;

    extern __shared__ char dyn[];
    const uint32_t dynB = (uint32_t)__cvta_generic_to_shared(dyn);
    const uint32_t base = (dynB + 1023u) & ~1023u;

    const int tid  = threadIdx.x;
    const int lane = tid & 31;
    const int warp = tid >> 5;
    const int warpM = warp % MWARP;
    const int warpN = warp / MWARP;
    const int rowBase = blockIdx.y * BM;
    const int colBase = blockIdx.x * BN;

    // cp.async mapping: 16B item i -> row i>>3, k-chunk i&7
    auto ldchunk = [&](int stage, int k0) {
        const uint32_t aB = base + stage * STG;
        const uint32_t bB = aB + ASZ;
#pragma unroll
        for (int p = 0; p < BM / 32; ++p) {
            const int i = tid + 256 * p;
            const int r = i >> 3, c = i & 7;
            cpasync16(aB + r * 128 + ((c ^ (r & 7)) << 4),
                      A + (size_t)(rowBase + r) * K + k0 + c * 8);
        }
#pragma unroll
        for (int p = 0; p < 4; ++p) {
            const int i = tid + 256 * p;
            const int r = i >> 3, c = i & 7;
            cpasync16(bB + r * 128 + ((c ^ (r & 7)) << 4),
                      W + (size_t)(colBase + r) * K + k0 + c * 8);
        }
        cp_commit();
    };

    float acc[2][NT][4];
#pragma unroll
    for (int i = 0; i < 2; ++i)
#pragma unroll
        for (int j = 0; j < NT; ++j)
#pragma unroll
            for (int c = 0; c < 4; ++c) acc[i][j][c] = 0.f;

    const int nCh = K / BK;
    ldchunk(0, 0);
    ldchunk(1, BK);

    // ldmatrix lane geometry
    const int arow = warpM * 32 + (lane & 15);               // + mt*16
    const int achk = lane >> 4;                              // + 2*ks
    const int brow = warpN * WN + (lane & 7) + ((lane >> 1) & 8);  // + p*16
    const int bchk = (lane >> 3) & 1;                        // + 2*ks

    for (int kc = 0; kc < nCh; ++kc) {
        if (kc == nCh - 1) cp_wait0(); else cp_wait1();
        __syncthreads();
        if (kc + 2 < nCh) ldchunk((kc + 2) % S, (kc + 2) * BK);

        const uint32_t aB = base + (kc % S) * STG;
        const uint32_t bB = aB + ASZ;

#pragma unroll
        for (int ks = 0; ks < 4; ++ks) {
            uint32_t af[2][4], bf[NT][2];
#pragma unroll
            for (int mt = 0; mt < 2; ++mt) {
                const int r = arow + mt * 16;
                const int c = 2 * ks + achk;
                ldsm4(af[mt][0], af[mt][1], af[mt][2], af[mt][3],
                      aB + r * 128 + ((c ^ (r & 7)) << 4));
            }
#pragma unroll
            for (int p = 0; p < NT / 2; ++p) {
                const int r = brow + p * 16;
                const int c = 2 * ks + bchk;
                ldsm4(bf[2 * p][0], bf[2 * p][1], bf[2 * p + 1][0], bf[2 * p + 1][1],
                      bB + r * 128 + ((c ^ (r & 7)) << 4));
            }
#pragma unroll
            for (int mt = 0; mt < 2; ++mt)
#pragma unroll
                for (int nt = 0; nt < NT; ++nt)
                    mma_f16(acc[mt][nt], af[mt], bf[nt]);
        }
    }

    // Epilogue: c0,c1 -> (m, 2fc),(m, 2fc+1); c2,c3 -> (m+8, ...)
    const int fr = lane >> 2;
    const int fc = lane & 3;
#pragma unroll
    for (int mt = 0; mt < 2; ++mt) {
        const int m = rowBase + warpM * 32 + mt * 16 + fr;
#pragma unroll
        for (int nt = 0; nt < NT; ++nt) {
            const int n = colBase + warpN * WN + nt * 8 + 2 * fc;
            const float bn0 = bias[n], bn1 = bias[n + 1];
            float v0 = acc[mt][nt][0] + bn0;
            float v1 = acc[mt][nt][1] + bn1;
            float v2 = acc[mt][nt][2] + bn0;
            float v3 = acc[mt][nt][3] + bn1;
            if (EPI >= 1) {
                v0 = tanhf(v0); v1 = tanhf(v1);
                v2 = tanhf(v2); v3 = tanhf(v3);
            }
            if (EPI == 2) {
                v0 *= mul[(size_t)m * N + n];
                v1 *= mul[(size_t)m * N + n + 1];
                v2 *= mul[(size_t)(m + 8) * N + n];
                v3 *= mul[(size_t)(m + 8) * N + n + 1];
            }
            if (EPI == 0) {
                float* C = (float*)Cv;
                float2 lo; lo.x = v0; lo.y = v1;
                float2 hi; hi.x = v2; hi.y = v3;
                *(float2*)(C + (size_t)m * N + n)       = lo;
                *(float2*)(C + (size_t)(m + 8) * N + n) = hi;
            } else {
                __half* C = (__half*)Cv;
                *(__half2*)(C + (size_t)m * N + n)       = __floats2half2_rn(v0, v1);
                *(__half2*)(C + (size_t)(m + 8) * N + n) = __floats2half2_rn(v2, v3);
            }
        }
    }
}

// ---------------------------------------------------------------------------
// fp32 -> fp16 elementwise copy (4 elems/thread)
// ---------------------------------------------------------------------------
__global__ void f2h_kernel(const float4* __restrict__ in, __half2* __restrict__ out, int n4)
{
    int i = blockIdx.x * blockDim.x + threadIdx.x;
    if (i < n4) {
        float4 v = in[i];
        out[2 * i]     = __floats2half2_rn(v.x, v.y);
        out[2 * i + 1] = __floats2half2_rn(v.z, v.w);
    }
}

// gather AGE rows via Endx + fp16 convert.  grid=M, block=192 (192*4 = 768)
__global__ void gather_h_kernel(const float* __restrict__ AGE,
                                const int* __restrict__ idx,
                                __half* __restrict__ out)
{
    const int m = blockIdx.x;
    const int r = idx[m];
    float4 v = ((const float4*)(AGE + (size_t)r * DIN))[threadIdx.x];
    __half2* o = (__half2*)(out + (size_t)m * DIN) + 2 * threadIdx.x;
    o[0] = __floats2half2_rn(v.x, v.y);
    o[1] = __floats2half2_rn(v.z, v.w);
}

// ---------------------------------------------------------------------------
// Per-row minmax scale + L2 normalize (fp32 in, fp16 out).
// One block (256 threads) per row of 768.
// ---------------------------------------------------------------------------
__global__ void rownorm_kernel(const float* __restrict__ Z, __half* __restrict__ Zh)
{
    __shared__ float shA[8], shB[8];
    const int t = threadIdx.x;
    const float* z = Z + (size_t)blockIdx.x * DIN;
    __half* zo = Zh + (size_t)blockIdx.x * DIN;

    float v0 = z[t], v1 = z[t + 256], v2 = z[t + 512];

    float mn = fminf(v0, fminf(v1, v2));
    float mx = fmaxf(v0, fmaxf(v1, v2));
#pragma unroll
    for (int o = 16; o > 0; o >>= 1) {
        mn = fminf(mn, __shfl_xor_sync(0xffffffffu, mn, o));
        mx = fmaxf(mx, __shfl_xor_sync(0xffffffffu, mx, o));
    }
    if ((t & 31) == 0) { shA[t >> 5] = mn; shB[t >> 5] = mx; }
    __syncthreads();
    float rmn = shA[0], rmx = shB[0];
#pragma unroll
    for (int i = 1; i < 8; ++i) { rmn = fminf(rmn, shA[i]); rmx = fmaxf(rmx, shB[i]); }

    const float sc = 1.f / (rmx - rmn);
    v0 = (v0 - rmn) * sc;
    v1 = (v1 - rmn) * sc;
    v2 = (v2 - rmn) * sc;

    float ss = v0 * v0 + v1 * v1 + v2 * v2;
#pragma unroll
    for (int o = 16; o > 0; o >>= 1)
        ss += __shfl_xor_sync(0xffffffffu, ss, o);
    __syncthreads();
    if ((t & 31) == 0) shA[t >> 5] = ss;
    __syncthreads();
    float tot = 0.f;
#pragma unroll
    for (int i = 0; i < 8; ++i) tot += shA[i];

    const float inv = 1.f / fmaxf(sqrtf(tot), 1e-12f);
    zo[t]       = __float2half(v0 * inv);
    zo[t + 256] = __float2half(v1 * inv);
    zo[t + 512] = __float2half(v2 * inv);
}

// ---------------------------------------------------------------------------
// o_f = h @ W_fc3^T + b_fc3   [8192, 50], K=256. Block handles 16 rows.
// ---------------------------------------------------------------------------
__global__ void fc3_kernel(const __half* __restrict__ h,
                           const float* __restrict__ W,
                           const float* __restrict__ b,
                           float* __restrict__ out)
{
    __shared__ float hs[16 * HID];
    const int r0 = blockIdx.x * 16;
    for (int i = threadIdx.x; i < 16 * HID / 2; i += 256) {
        __half2 p = ((const __half2*)(h + (size_t)r0 * HID))[i];
        float2 f = __half22float2(p);
        hs[2 * i] = f.x; hs[2 * i + 1] = f.y;
    }
    __syncthreads();

    for (int o = threadIdx.x; o < 16 * OUTFE; o += 256) {
        const int r = o / OUTFE, c = o % OUTFE;
        const float* w = W + (size_t)c * HID;
        const float* hr = hs + r * HID;
        float acc = 0.f;
#pragma unroll 8
        for (int k = 0; k < HID; ++k) acc += hr[k] * w[k];
        out[(size_t)(r0 + r) * OUTFE + c] = acc + b[c];
    }
}

// ---------------------------------------------------------------------------
extern "C" void kernel_launch(void* const* d_in, const int* in_sizes, int n_in,
                              void* d_out, int out_size)
{
    const float* t_in   = (const float*)d_in[0];
    const float* AGE    = (const float*)d_in[1];
    const int*   Endx   = (const int*)  d_in[2];
    const float* W_age  = (const float*)d_in[3];
    const float* b_age  = (const float*)d_in[4];
    const float* W_prjT = (const float*)d_in[5];
    const float* b_prjT = (const float*)d_in[6];
    const float* W_prjL = (const float*)d_in[7];
    const float* b_prjL = (const float*)d_in[8];
    const float* outW   = (const float*)d_in[9];
    const float* outb   = (const float*)d_in[10];
    const float* W_fc3  = (const float*)d_in[11];
    const float* b_fc3  = (const float*)d_in[12];

    float* o_c = (float*)d_out;
    float* o_f = o_c + (size_t)NN * MM;

    float *Z;
    __half *Zh, *EW, *h, *tH, *Ag, *Wa, *Wt, *Wl;
    cudaGetSymbolAddress((void**)&Z,  g_Z);
    cudaGetSymbolAddress((void**)&Zh, g_Zh);
    cudaGetSymbolAddress((void**)&EW, g_EW);
    cudaGetSymbolAddress((void**)&h,  g_h);
    cudaGetSymbolAddress((void**)&tH, g_t);
    cudaGetSymbolAddress((void**)&Ag, g_Ag);
    cudaGetSymbolAddress((void**)&Wa, g_Wa);
    cudaGetSymbolAddress((void**)&Wt, g_Wt);
    cudaGetSymbolAddress((void**)&Wl, g_Wl);

    // dynamic smem: 3 stages * stage size + 1KB alignment slack
    constexpr int SMEM128 = 3 * 32768 + 1024;   // BM=128
    constexpr int SMEM64  = 3 * 24576 + 1024;   // BM=64
    cudaFuncSetAttribute(gemm_h<128, 0>, cudaFuncAttributeMaxDynamicSharedMemorySize, SMEM128);
    cudaFuncSetAttribute(gemm_h<64, 0>,  cudaFuncAttributeMaxDynamicSharedMemorySize, SMEM64);
    cudaFuncSetAttribute(gemm_h<64, 1>,  cudaFuncAttributeMaxDynamicSharedMemorySize, SMEM64);
    cudaFuncSetAttribute(gemm_h<64, 2>,  cudaFuncAttributeMaxDynamicSharedMemorySize, SMEM64);

    // 0) fp16 conversion of GEMM operands
    {
        int n4 = NN * DIN / 4;
        f2h_kernel<<<(n4 + 255) / 256, 256>>>((const float4*)t_in, (__half2*)tH, n4);
        n4 = DIN * DIN / 4;
        f2h_kernel<<<(n4 + 255) / 256, 256>>>((const float4*)W_age, (__half2*)Wa, n4);
        n4 = HID * DIN / 4;
        f2h_kernel<<<(n4 + 255) / 256, 256>>>((const float4*)W_prjT, (__half2*)Wt, n4);
        f2h_kernel<<<(n4 + 255) / 256, 256>>>((const float4*)W_prjL, (__half2*)Wl, n4);
        gather_h_kernel<<<MM, 192>>>(AGE, Endx, Ag);
    }

    // 1) Z = Ag @ Wa^T + b_age   [4096, 768], K=768 (fp32 out) — 384 blocks
    gemm_h<64, 0><<<dim3(DIN / 128, MM / 64), 256, SMEM64>>>(Ag, Wa, b_age, nullptr, Z, DIN, DIN);

    // 2) per-row minmax scale + L2 normalize -> fp16
    rownorm_kernel<<<MM, 256>>>(Z, Zh);

    // 3) EW = tanh(Zh @ Wl^T + b_prjL) * outW   [4096, 256], K=768 — 128 blocks
    gemm_h<64, 2><<<dim3(HID / 128, MM / 64), 256, SMEM64>>>(Zh, Wl, b_prjL, outW, EW, HID, DIN);

    // 4) h = tanh(tH @ Wt^T + b_prjT)   [8192, 256], K=768 — 256 blocks
    gemm_h<64, 1><<<dim3(HID / 128, NN / 64), 256, SMEM64>>>(tH, Wt, b_prjT, nullptr, h, HID, DIN);

    // 5) o_c = h @ EW^T + outb   [8192, 4096], K=256 — 2048 blocks
    gemm_h<128, 0><<<dim3(MM / 128, NN / 128), 256, SMEM128>>>(h, EW, outb, nullptr, o_c, MM, HID);

    // 6) o_f = h @ W_fc3^T + b_fc3   [8192, 50], K=256
    fc3_kernel<<<NN / 16, 256>>>(h, W_fc3, b_fc3, o_f);
}

// round 12
// speedup vs baseline: 2.2503x; 1.0355x over previous
#include <cuda_runtime.h>
#include <cuda_fp16.h>
#include <cstdint>

#define DIN 768
#define HID 256
#define NN  8192
#define MM  4096
#define OUTFE 50

// Scratch (device globals: no allocations allowed)
__device__ __align__(256) float  g_Z  [(size_t)MM * DIN];  // gemm1 out (fp32)
__device__ __align__(256) __half g_Zh [(size_t)MM * DIN];  // rownorm out (fp16)
__device__ __align__(256) __half g_EW [(size_t)MM * HID];  // tanh(E)*outW (fp16)
__device__ __align__(256) __half g_h  [(size_t)NN * HID];  // tanh(t@WprjT^T+b) (fp16)
__device__ __align__(256) __half g_t  [(size_t)NN * DIN];  // fp16 t
__device__ __align__(256) __half g_Ag [(size_t)MM * DIN];  // fp16 gathered AGE rows
__device__ __align__(256) __half g_Wa [(size_t)DIN * DIN]; // fp16 W_age
__device__ __align__(256) __half g_Wt [(size_t)HID * DIN]; // fp16 W_prjT
__device__ __align__(256) __half g_Wl [(size_t)HID * DIN]; // fp16 W_prjL

__device__ __forceinline__ void cpasync16(uint32_t d, const void* g) {
    asm volatile("cp.async.cg.shared.global [%0], [%1], 16;" :: "r"(d), "l"(g));
}
__device__ __forceinline__ void cp_commit() { asm volatile("cp.async.commit_group;"); }
__device__ __forceinline__ void cp_wait1()  { asm volatile("cp.async.wait_group 1;"); }
__device__ __forceinline__ void cp_wait0()  { asm volatile("cp.async.wait_group 0;"); }

__device__ __forceinline__ void ldsm4(uint32_t& r0, uint32_t& r1, uint32_t& r2, uint32_t& r3,
                                      uint32_t addr) {
    asm volatile("ldmatrix.sync.aligned.m8n8.x4.shared.b16 {%0,%1,%2,%3}, [%4];"
                 : "=r"(r0), "=r"(r1), "=r"(r2), "=r"(r3) : "r"(addr));
}

__device__ __forceinline__ void mma_f16(float* d, const uint32_t* a, const uint32_t* b) {
    asm volatile(
        "mma.sync.aligned.m16n8k16.row.col.f32.f16.f16.f32 "
        "{%0,%1,%2,%3}, {%4,%5,%6,%7}, {%8,%9}, {%0,%1,%2,%3};"
        : "+f"(d[0]), "+f"(d[1]), "+f"(d[2]), "+f"(d[3])
        : "r"(a[0]), "r"(a[1]), "r"(a[2]), "r"(a[3]), "r"(b[0]), "r"(b[1]));
}

// ---------------------------------------------------------------------------
// fp16 tensor-core GEMM body (mma.sync m16n8k16 + ldmatrix), 3-stage cp.async.
//   C[m,n] = epi( sum_k A[m,k]*W[n,k] + bias[n] )
//   EPI: 0 = none, fp32 out; 1 = tanh, fp16 out; 2 = tanh*mul[m*N+n], fp16 out
// BN=128, BK=64 (128B rows, XOR-16B swizzle), 256 threads (8 warps).
// BM=128: warps 4(M)x2(N), NT=8.  BM=64: warps 2(M)x4(N), NT=4.
// ---------------------------------------------------------------------------
template<int BM, int EPI>
__device__ __forceinline__ void gemm_body(
    int bx, int by,
    const __half* __restrict__ A, const __half* __restrict__ W,
    const float* __restrict__ bias, const float* __restrict__ mul,
    void* __restrict__ Cv, int N, int K, char* dyn)
{
    constexpr int BN = 128, BK = 64, S = 3;
    constexpr int MWARP = BM / 32;
    constexpr int NWARP = 8 / MWARP;
    constexpr int WN    = BN / NWARP;
    constexpr int NT    = WN / 8;
    constexpr int ASZ = BM * BK * 2;
    constexpr int BSZ = BN * BK * 2;
    constexpr int STG = ASZ + BSZ;

    const uint32_t dynB = (uint32_t)__cvta_generic_to_shared(dyn);
    const uint32_t base = (dynB + 1023u) & ~1023u;

    const int tid  = threadIdx.x;
    const int lane = tid & 31;
    const int warp = tid >> 5;
    const int warpM = warp % MWARP;
    const int warpN = warp / MWARP;
    const int rowBase = by * BM;
    const int colBase = bx * BN;

    auto ldchunk = [&](int stage, int k0) {
        const uint32_t aB = base + stage * STG;
        const uint32_t bB = aB + ASZ;
#pragma unroll
        for (int p = 0; p < BM / 32; ++p) {
            const int i = tid + 256 * p;
            const int r = i >> 3, c = i & 7;
            cpasync16(aB + r * 128 + ((c ^ (r & 7)) << 4),
                      A + (size_t)(rowBase + r) * K + k0 + c * 8);
        }
#pragma unroll
        for (int p = 0; p < 4; ++p) {
            const int i = tid + 256 * p;
            const int r = i >> 3, c = i & 7;
            cpasync16(bB + r * 128 + ((c ^ (r & 7)) << 4),
                      W + (size_t)(colBase + r) * K + k0 + c * 8);
        }
        cp_commit();
    };

    float acc[2][NT][4];
#pragma unroll
    for (int i = 0; i < 2; ++i)
#pragma unroll
        for (int j = 0; j < NT; ++j)
#pragma unroll
            for (int c = 0; c < 4; ++c) acc[i][j][c] = 0.f;

    const int nCh = K / BK;
    ldchunk(0, 0);
    ldchunk(1, BK);

    const int arow = warpM * 32 + (lane & 15);
    const int achk = lane >> 4;
    const int brow = warpN * WN + (lane & 7) + ((lane >> 1) & 8);
    const int bchk = (lane >> 3) & 1;

    for (int kc = 0; kc < nCh; ++kc) {
        if (kc == nCh - 1) cp_wait0(); else cp_wait1();
        __syncthreads();
        if (kc + 2 < nCh) ldchunk((kc + 2) % S, (kc + 2) * BK);

        const uint32_t aB = base + (kc % S) * STG;
        const uint32_t bB = aB + ASZ;

#pragma unroll
        for (int ks = 0; ks < 4; ++ks) {
            uint32_t af[2][4], bf[NT][2];
#pragma unroll
            for (int mt = 0; mt < 2; ++mt) {
                const int r = arow + mt * 16;
                const int c = 2 * ks + achk;
                ldsm4(af[mt][0], af[mt][1], af[mt][2], af[mt][3],
                      aB + r * 128 + ((c ^ (r & 7)) << 4));
            }
#pragma unroll
            for (int p = 0; p < NT / 2; ++p) {
                const int r = brow + p * 16;
                const int c = 2 * ks + bchk;
                ldsm4(bf[2 * p][0], bf[2 * p][1], bf[2 * p + 1][0], bf[2 * p + 1][1],
                      bB + r * 128 + ((c ^ (r & 7)) << 4));
            }
#pragma unroll
            for (int mt = 0; mt < 2; ++mt)
#pragma unroll
                for (int nt = 0; nt < NT; ++nt)
                    mma_f16(acc[mt][nt], af[mt], bf[nt]);
        }
    }

    const int fr = lane >> 2;
    const int fc = lane & 3;
#pragma unroll
    for (int mt = 0; mt < 2; ++mt) {
        const int m = rowBase + warpM * 32 + mt * 16 + fr;
#pragma unroll
        for (int nt = 0; nt < NT; ++nt) {
            const int n = colBase + warpN * WN + nt * 8 + 2 * fc;
            const float bn0 = bias[n], bn1 = bias[n + 1];
            float v0 = acc[mt][nt][0] + bn0;
            float v1 = acc[mt][nt][1] + bn1;
            float v2 = acc[mt][nt][2] + bn0;
            float v3 = acc[mt][nt][3] + bn1;
            if (EPI >= 1) {
                v0 = tanhf(v0); v1 = tanhf(v1);
                v2 = tanhf(v2); v3 = tanhf(v3);
            }
            if (EPI == 2) {
                v0 *= mul[(size_t)m * N + n];
                v1 *= mul[(size_t)m * N + n + 1];
                v2 *= mul[(size_t)(m + 8) * N + n];
                v3 *= mul[(size_t)(m + 8) * N + n + 1];
            }
            if (EPI == 0) {
                float* C = (float*)Cv;
                float2 lo; lo.x = v0; lo.y = v1;
                float2 hi; hi.x = v2; hi.y = v3;
                *(float2*)(C + (size_t)m * N + n)       = lo;
                *(float2*)(C + (size_t)(m + 8) * N + n) = hi;
            } else {
                __half* C = (__half*)Cv;
                *(__half2*)(C + (size_t)m * N + n)       = __floats2half2_rn(v0, v1);
                *(__half2*)(C + (size_t)(m + 8) * N + n) = __floats2half2_rn(v2, v3);
            }
        }
    }
}

// o_c standalone: BM=128, EPI=0
__global__ void __launch_bounds__(256, 2)
gemm_oc(const __half* __restrict__ A, const __half* __restrict__ W,
        const float* __restrict__ bias, float* __restrict__ C, int N, int K)
{
    extern __shared__ char dyn[];
    gemm_body<128, 0>(blockIdx.x, blockIdx.y, A, W, bias, nullptr, C, N, K, dyn);
}

// fused1: blocks [0,384) -> gemm1 (Z = Ag@Wa^T + b_age, grid 6x64)
//         blocks [384,640) -> gemm4 (h = tanh(t@Wt^T + b_prjT), grid 2x128)
__global__ void __launch_bounds__(256, 2)
fused1_kernel(const __half* __restrict__ Ag, const __half* __restrict__ Wa,
              const float* __restrict__ b_age, float* __restrict__ Z,
              const __half* __restrict__ tH, const __half* __restrict__ Wt,
              const float* __restrict__ b_prjT, __half* __restrict__ h)
{
    extern __shared__ char dyn[];
    const int b = blockIdx.x;
    if (b < 384) {
        gemm_body<64, 0>(b % 6, b / 6, Ag, Wa, b_age, nullptr, Z, DIN, DIN, dyn);
    } else {
        const int r = b - 384;
        gemm_body<64, 1>(r % 2, r / 2, tH, Wt, b_prjT, nullptr, h, HID, DIN, dyn);
    }
}

// fc3 body using dynamic smem: o_f = h @ W_fc3^T + b_fc3, 16 rows per block
__device__ __forceinline__ void fc3_body(int blk, const __half* __restrict__ h,
                                         const float* __restrict__ W,
                                         const float* __restrict__ b,
                                         float* __restrict__ out, char* dyn)
{
    float* hs = (float*)dyn;   // 16*HID floats = 16 KB
    const int r0 = blk * 16;
    for (int i = threadIdx.x; i < 16 * HID / 2; i += 256) {
        __half2 p = ((const __half2*)(h + (size_t)r0 * HID))[i];
        float2 f = __half22float2(p);
        hs[2 * i] = f.x; hs[2 * i + 1] = f.y;
    }
    __syncthreads();

    for (int o = threadIdx.x; o < 16 * OUTFE; o += 256) {
        const int r = o / OUTFE, c = o % OUTFE;
        const float* w = W + (size_t)c * HID;
        const float* hr = hs + r * HID;
        float acc = 0.f;
#pragma unroll 8
        for (int k = 0; k < HID; ++k) acc += hr[k] * w[k];
        out[(size_t)(r0 + r) * OUTFE + c] = acc + b[c];
    }
}

// fused2: blocks [0,128) -> gemm3 (EW = tanh(Zh@Wl^T + b_prjL)*outW, grid 2x64)
//         blocks [128,640) -> fc3 (512 blocks)
__global__ void __launch_bounds__(256, 2)
fused2_kernel(const __half* __restrict__ Zh, const __half* __restrict__ Wl,
              const float* __restrict__ b_prjL, const float* __restrict__ outW,
              __half* __restrict__ EW,
              const __half* __restrict__ h, const float* __restrict__ W_fc3,
              const float* __restrict__ b_fc3, float* __restrict__ o_f)
{
    extern __shared__ char dyn[];
    const int b = blockIdx.x;
    if (b < 128) {
        gemm_body<64, 2>(b % 2, b / 2, Zh, Wl, b_prjL, outW, EW, HID, DIN, dyn);
    } else {
        fc3_body(b - 128, h, W_fc3, b_fc3, o_f, dyn);
    }
}

// ---------------------------------------------------------------------------
// All operand conversions in ONE launch (range-dispatched, 256 threads):
//  job0: t -> fp16        (6144 blocks)
//  job1: W_age -> fp16    (576)
//  job2: W_prjT -> fp16   (192)
//  job3: W_prjL -> fp16   (192)
//  job4: gather AGE[Endx] -> fp16 (3072 blocks; item = (row, float4-col))
// ---------------------------------------------------------------------------
#define CV_T   6144
#define CV_WA  576
#define CV_WT  192
#define CV_WL  192
#define CV_G   3072
__global__ void __launch_bounds__(256)
convert_all(const float* __restrict__ t_in, const float* __restrict__ W_age,
            const float* __restrict__ W_prjT, const float* __restrict__ W_prjL,
            const float* __restrict__ AGE, const int* __restrict__ Endx,
            __half* __restrict__ tH, __half* __restrict__ Wa,
            __half* __restrict__ Wt, __half* __restrict__ Wl,
            __half* __restrict__ Ag)
{
    int b = blockIdx.x;
    const float4* src;
    __half2* dst;
    if (b < CV_T) {
        src = (const float4*)t_in;  dst = (__half2*)tH;
    } else if (b < CV_T + CV_WA) {
        b -= CV_T; src = (const float4*)W_age; dst = (__half2*)Wa;
    } else if (b < CV_T + CV_WA + CV_WT) {
        b -= CV_T + CV_WA; src = (const float4*)W_prjT; dst = (__half2*)Wt;
    } else if (b < CV_T + CV_WA + CV_WT + CV_WL) {
        b -= CV_T + CV_WA + CV_WT; src = (const float4*)W_prjL; dst = (__half2*)Wl;
    } else {
        // gather: item i covers (row m = i/192, float4-col c = i%192)
        const int i = (b - (CV_T + CV_WA + CV_WT + CV_WL)) * 256 + threadIdx.x;
        const int m = i / 192, c = i % 192;
        const int r = Endx[m];
        float4 v = ((const float4*)(AGE + (size_t)r * DIN))[c];
        __half2* o = (__half2*)(Ag + (size_t)m * DIN) + 2 * c;
        o[0] = __floats2half2_rn(v.x, v.y);
        o[1] = __floats2half2_rn(v.z, v.w);
        return;
    }
    const int i = b * 256 + threadIdx.x;
    float4 v = src[i];
    dst[2 * i]     = __floats2half2_rn(v.x, v.y);
    dst[2 * i + 1] = __floats2half2_rn(v.z, v.w);
}

// ---------------------------------------------------------------------------
// Per-row minmax scale + L2 normalize (fp32 in, fp16 out).
// ---------------------------------------------------------------------------
__global__ void rownorm_kernel(const float* __restrict__ Z, __half* __restrict__ Zh)
{
    __shared__ float shA[8], shB[8];
    const int t = threadIdx.x;
    const float* z = Z + (size_t)blockIdx.x * DIN;
    __half* zo = Zh + (size_t)blockIdx.x * DIN;

    float v0 = z[t], v1 = z[t + 256], v2 = z[t + 512];

    float mn = fminf(v0, fminf(v1, v2));
    float mx = fmaxf(v0, fmaxf(v1, v2));
#pragma unroll
    for (int o = 16; o > 0; o >>= 1) {
        mn = fminf(mn, __shfl_xor_sync(0xffffffffu, mn, o));
        mx = fmaxf(mx, __shfl_xor_sync(0xffffffffu, mx, o));
    }
    if ((t & 31) == 0) { shA[t >> 5] = mn; shB[t >> 5] = mx; }
    __syncthreads();
    float rmn = shA[0], rmx = shB[0];
#pragma unroll
    for (int i = 1; i < 8; ++i) { rmn = fminf(rmn, shA[i]); rmx = fmaxf(rmx, shB[i]); }

    const float sc = 1.f / (rmx - rmn);
    v0 = (v0 - rmn) * sc;
    v1 = (v1 - rmn) * sc;
    v2 = (v2 - rmn) * sc;

    float ss = v0 * v0 + v1 * v1 + v2 * v2;
#pragma unroll
    for (int o = 16; o > 0; o >>= 1)
        ss += __shfl_xor_sync(0xffffffffu, ss, o);
    __syncthreads();
    if ((t & 31) == 0) shA[t >> 5] = ss;
    __syncthreads();
    float tot = 0.f;
#pragma unroll
    for (int i = 0; i < 8; ++i) tot += shA[i];

    const float inv = 1.f / fmaxf(sqrtf(tot), 1e-12f);
    zo[t]       = __float2half(v0 * inv);
    zo[t + 256] = __float2half(v1 * inv);
    zo[t + 512] = __float2half(v2 * inv);
}

// ---------------------------------------------------------------------------
extern "C" void kernel_launch(void* const* d_in, const int* in_sizes, int n_in,
                              void* d_out, int out_size)
{
    const float* t_in   = (const float*)d_in[0];
    const float* AGE    = (const float*)d_in[1];
    const int*   Endx   = (const int*)  d_in[2];
    const float* W_age  = (const float*)d_in[3];
    const float* b_age  = (const float*)d_in[4];
    const float* W_prjT = (const float*)d_in[5];
    const float* b_prjT = (const float*)d_in[6];
    const float* W_prjL = (const float*)d_in[7];
    const float* b_prjL = (const float*)d_in[8];
    const float* outW   = (const float*)d_in[9];
    const float* outb   = (const float*)d_in[10];
    const float* W_fc3  = (const float*)d_in[11];
    const float* b_fc3  = (const float*)d_in[12];

    float* o_c = (float*)d_out;
    float* o_f = o_c + (size_t)NN * MM;

    float *Z;
    __half *Zh, *EW, *h, *tH, *Ag, *Wa, *Wt, *Wl;
    cudaGetSymbolAddress((void**)&Z,  g_Z);
    cudaGetSymbolAddress((void**)&Zh, g_Zh);
    cudaGetSymbolAddress((void**)&EW, g_EW);
    cudaGetSymbolAddress((void**)&h,  g_h);
    cudaGetSymbolAddress((void**)&tH, g_t);
    cudaGetSymbolAddress((void**)&Ag, g_Ag);
    cudaGetSymbolAddress((void**)&Wa, g_Wa);
    cudaGetSymbolAddress((void**)&Wt, g_Wt);
    cudaGetSymbolAddress((void**)&Wl, g_Wl);

    constexpr int SMEM128 = 3 * 32768 + 1024;   // BM=128 stage set
    constexpr int SMEM64  = 3 * 24576 + 1024;   // BM=64 stage set
    cudaFuncSetAttribute(gemm_oc,       cudaFuncAttributeMaxDynamicSharedMemorySize, SMEM128);
    cudaFuncSetAttribute(fused1_kernel, cudaFuncAttributeMaxDynamicSharedMemorySize, SMEM64);
    cudaFuncSetAttribute(fused2_kernel, cudaFuncAttributeMaxDynamicSharedMemorySize, SMEM64);

    // 1) all operand conversions (5 jobs, 1 launch)
    convert_all<<<CV_T + CV_WA + CV_WT + CV_WL + CV_G, 256>>>(
        t_in, W_age, W_prjT, W_prjL, AGE, Endx, tH, Wa, Wt, Wl, Ag);

    // 2) gemm1 (Z) + gemm4 (h) fused — 640 blocks
    fused1_kernel<<<640, 256, SMEM64>>>(Ag, Wa, b_age, Z, tH, Wt, b_prjT, h);

    // 3) per-row minmax scale + L2 normalize -> fp16
    rownorm_kernel<<<MM, 256>>>(Z, Zh);

    // 4) gemm3 (EW) + fc3 (o_f) fused — 640 blocks
    fused2_kernel<<<640, 256, SMEM64>>>(Zh, Wl, b_prjL, outW, EW, h, W_fc3, b_fc3, o_f);

    // 5) o_c = h @ EW^T + outb — 2048 blocks
    gemm_oc<<<dim3(MM / 128, NN / 128), 256, SMEM128>>>(h, EW, outb, o_c, MM, HID);
}

// round 16
// speedup vs baseline: 8.2603x; 3.6707x over previous
#include <cuda_runtime.h>
#include <cuda_fp16.h>
#include <cstdint>

#define DIN 768
#define HID 256
#define NN  8192
#define MM  4096
#define OUTFE 50

// Scratch (device globals: no allocations allowed)
__device__ __align__(256) float  g_Z  [(size_t)MM * DIN];  // gemm1 out (fp32)
__device__ __align__(256) __half g_Zh [(size_t)MM * DIN];  // rownorm out (fp16)
__device__ __align__(256) __half g_EW [(size_t)MM * HID];  // tanh(E)*outW (fp16)
__device__ __align__(256) __half g_h  [(size_t)NN * HID];  // tanh(t@WprjT^T+b) (fp16)
__device__ __align__(256) __half g_t  [(size_t)NN * DIN];  // fp16 t
__device__ __align__(256) __half g_Ag [(size_t)MM * DIN];  // fp16 gathered AGE rows
__device__ __align__(256) __half g_Wa [(size_t)DIN * DIN]; // fp16 W_age
__device__ __align__(256) __half g_Wt [(size_t)HID * DIN]; // fp16 W_prjT
__device__ __align__(256) __half g_Wl [(size_t)HID * DIN]; // fp16 W_prjL

__device__ __forceinline__ void cpasync16(uint32_t d, const void* g) {
    asm volatile("cp.async.cg.shared.global [%0], [%1], 16;" :: "r"(d), "l"(g));
}
__device__ __forceinline__ void cp_commit() { asm volatile("cp.async.commit_group;"); }
__device__ __forceinline__ void cp_wait1()  { asm volatile("cp.async.wait_group 1;"); }
__device__ __forceinline__ void cp_wait0()  { asm volatile("cp.async.wait_group 0;"); }

__device__ __forceinline__ void ldsm4(uint32_t& r0, uint32_t& r1, uint32_t& r2, uint32_t& r3,
                                      uint32_t addr) {
    asm volatile("ldmatrix.sync.aligned.m8n8.x4.shared.b16 {%0,%1,%2,%3}, [%4];"
                 : "=r"(r0), "=r"(r1), "=r"(r2), "=r"(r3) : "r"(addr));
}

__device__ __forceinline__ void mma_f16(float* d, const uint32_t* a, const uint32_t* b) {
    asm volatile(
        "mma.sync.aligned.m16n8k16.row.col.f32.f16.f16.f32 "
        "{%0,%1,%2,%3}, {%4,%5,%6,%7}, {%8,%9}, {%0,%1,%2,%3};"
        : "+f"(d[0]), "+f"(d[1]), "+f"(d[2]), "+f"(d[3])
        : "r"(a[0]), "r"(a[1]), "r"(a[2]), "r"(a[3]), "r"(b[0]), "r"(b[1]));
}

// ---------------------------------------------------------------------------
// fp16 tensor-core GEMM body (mma.sync m16n8k16 + ldmatrix), 3-stage cp.async.
//   C[m,n] = epi( sum_k A[m,k]*W[n,k] + bias[n] )
//   EPI: 0 = none, fp32 out; 1 = tanh, fp16 out; 2 = tanh*mul[m*N+n], fp16 out
// BN=128, BK=64 (128B rows, XOR-16B swizzle), 256 threads (8 warps).
// BM=128: warps 4(M)x2(N), NT=8.  BM=64: warps 2(M)x4(N), NT=4.
// ---------------------------------------------------------------------------
template<int BM, int EPI>
__device__ __forceinline__ void gemm_body(
    int bx, int by,
    const __half* __restrict__ A, const __half* __restrict__ W,
    const float* __restrict__ bias, const float* __restrict__ mul,
    void* __restrict__ Cv, int N, int K, char* dyn)
{
    constexpr int BN = 128, BK = 64, S = 3;
    constexpr int MWARP = BM / 32;
    constexpr int NWARP = 8 / MWARP;
    constexpr int WN    = BN / NWARP;
    constexpr int NT    = WN / 8;
    constexpr int ASZ = BM * BK * 2;
    constexpr int BSZ = BN * BK * 2;
    constexpr int STG = ASZ + BSZ;

    const uint32_t dynB = (uint32_t)__cvta_generic_to_shared(dyn);
    const uint32_t base = (dynB + 1023u) & ~1023u;

    const int tid  = threadIdx.x;
    const int lane = tid & 31;
    const int warp = tid >> 5;
    const int warpM = warp % MWARP;
    const int warpN = warp / MWARP;
    const int rowBase = by * BM;
    const int colBase = bx * BN;

    auto ldchunk = [&](int stage, int k0) {
        const uint32_t aB = base + stage * STG;
        const uint32_t bB = aB + ASZ;
#pragma unroll
        for (int p = 0; p < BM / 32; ++p) {
            const int i = tid + 256 * p;
            const int r = i >> 3, c = i & 7;
            cpasync16(aB + r * 128 + ((c ^ (r & 7)) << 4),
                      A + (size_t)(rowBase + r) * K + k0 + c * 8);
        }
#pragma unroll
        for (int p = 0; p < 4; ++p) {
            const int i = tid + 256 * p;
            const int r = i >> 3, c = i & 7;
            cpasync16(bB + r * 128 + ((c ^ (r & 7)) << 4),
                      W + (size_t)(colBase + r) * K + k0 + c * 8);
        }
        cp_commit();
    };

    float acc[2][NT][4];
#pragma unroll
    for (int i = 0; i < 2; ++i)
#pragma unroll
        for (int j = 0; j < NT; ++j)
#pragma unroll
            for (int c = 0; c < 4; ++c) acc[i][j][c] = 0.f;

    const int nCh = K / BK;
    ldchunk(0, 0);
    ldchunk(1, BK);

    const int arow = warpM * 32 + (lane & 15);
    const int achk = lane >> 4;
    const int brow = warpN * WN + (lane & 7) + ((lane >> 1) & 8);
    const int bchk = (lane >> 3) & 1;

    for (int kc = 0; kc < nCh; ++kc) {
        if (kc == nCh - 1) cp_wait0(); else cp_wait1();
        __syncthreads();
        if (kc + 2 < nCh) ldchunk((kc + 2) % S, (kc + 2) * BK);

        const uint32_t aB = base + (kc % S) * STG;
        const uint32_t bB = aB + ASZ;

#pragma unroll
        for (int ks = 0; ks < 4; ++ks) {
            uint32_t af[2][4], bf[NT][2];
#pragma unroll
            for (int mt = 0; mt < 2; ++mt) {
                const int r = arow + mt * 16;
                const int c = 2 * ks + achk;
                ldsm4(af[mt][0], af[mt][1], af[mt][2], af[mt][3],
                      aB + r * 128 + ((c ^ (r & 7)) << 4));
            }
#pragma unroll
            for (int p = 0; p < NT / 2; ++p) {
                const int r = brow + p * 16;
                const int c = 2 * ks + bchk;
                ldsm4(bf[2 * p][0], bf[2 * p][1], bf[2 * p + 1][0], bf[2 * p + 1][1],
                      bB + r * 128 + ((c ^ (r & 7)) << 4));
            }
#pragma unroll
            for (int mt = 0; mt < 2; ++mt)
#pragma unroll
                for (int nt = 0; nt < NT; ++nt)
                    mma_f16(acc[mt][nt], af[mt], bf[nt]);
        }
    }

    const int fr = lane >> 2;
    const int fc = lane & 3;
#pragma unroll
    for (int mt = 0; mt < 2; ++mt) {
        const int m = rowBase + warpM * 32 + mt * 16 + fr;
#pragma unroll
        for (int nt = 0; nt < NT; ++nt) {
            const int n = colBase + warpN * WN + nt * 8 + 2 * fc;
            const float bn0 = bias[n], bn1 = bias[n + 1];
            float v0 = acc[mt][nt][0] + bn0;
            float v1 = acc[mt][nt][1] + bn1;
            float v2 = acc[mt][nt][2] + bn0;
            float v3 = acc[mt][nt][3] + bn1;
            if (EPI >= 1) {
                v0 = tanhf(v0); v1 = tanhf(v1);
                v2 = tanhf(v2); v3 = tanhf(v3);
            }
            if (EPI == 2) {
                v0 *= mul[(size_t)m * N + n];
                v1 *= mul[(size_t)m * N + n + 1];
                v2 *= mul[(size_t)(m + 8) * N + n];
                v3 *= mul[(size_t)(m + 8) * N + n + 1];
            }
            if (EPI == 0) {
                float* C = (float*)Cv;
                float2 lo; lo.x = v0; lo.y = v1;
                float2 hi; hi.x = v2; hi.y = v3;
                *(float2*)(C + (size_t)m * N + n)       = lo;
                *(float2*)(C + (size_t)(m + 8) * N + n) = hi;
            } else {
                __half* C = (__half*)Cv;
                *(__half2*)(C + (size_t)m * N + n)       = __floats2half2_rn(v0, v1);
                *(__half2*)(C + (size_t)(m + 8) * N + n) = __floats2half2_rn(v2, v3);
            }
        }
    }
}

// o_c standalone: BM=128, EPI=0
__global__ void __launch_bounds__(256, 2)
gemm_oc(const __half* __restrict__ A, const __half* __restrict__ W,
        const float* __restrict__ bias, float* __restrict__ C, int N, int K)
{
    extern __shared__ char dyn[];
    gemm_body<128, 0>(blockIdx.x, blockIdx.y, A, W, bias, nullptr, C, N, K, dyn);
}

// fused1: blocks [0,384) -> gemm1 (Z = Ag@Wa^T + b_age, grid 6x64)
//         blocks [384,640) -> gemm4 (h = tanh(t@Wt^T + b_prjT), grid 2x128)
__global__ void __launch_bounds__(256, 2)
fused1_kernel(const __half* __restrict__ Ag, const __half* __restrict__ Wa,
              const float* __restrict__ b_age, float* __restrict__ Z,
              const __half* __restrict__ tH, const __half* __restrict__ Wt,
              const float* __restrict__ b_prjT, __half* __restrict__ h)
{
    extern __shared__ char dyn[];
    const int b = blockIdx.x;
    if (b < 384) {
        gemm_body<64, 0>(b % 6, b / 6, Ag, Wa, b_age, nullptr, Z, DIN, DIN, dyn);
    } else {
        const int r = b - 384;
        gemm_body<64, 1>(r % 2, r / 2, tH, Wt, b_prjT, nullptr, h, HID, DIN, dyn);
    }
}

// ---------------------------------------------------------------------------
// fc3 body, rewritten: W_fc3 (50x256 fp32 = 50KB) cooperatively staged into
// smem ONCE per block; each warp owns 2 rows of h in registers and computes
// all 50 dots with conflict-free LDS.128 W reads + shfl reductions.
// 16 rows per block (8 warps x 2 rows). Lane k-slices: [lane*4, +4) and
// [128+lane*4, +4) -> contiguous 16B per lane in both halves.
// ---------------------------------------------------------------------------
__device__ __forceinline__ void fc3_body(int blk, const __half* __restrict__ h,
                                         const float* __restrict__ W,
                                         const float* __restrict__ b,
                                         float* __restrict__ out, char* dyn)
{
    float* Ws = (float*)dyn;   // OUTFE*HID floats = 51200 B
    for (int i = threadIdx.x; i < OUTFE * HID / 4; i += 256)
        ((float4*)Ws)[i] = ((const float4*)W)[i];
    __syncthreads();

    const int lane = threadIdx.x & 31;
    const int warp = threadIdx.x >> 5;
    const int r0 = blk * 16 + warp * 2;

    // h rows -> registers: 4 halfs at k=lane*4 and 4 at k=128+lane*4, per row
    float h0[8], h1[8];
    {
        const uint32_t* p0 = (const uint32_t*)(h + (size_t)r0 * HID);
        const uint32_t* p1 = (const uint32_t*)(h + (size_t)(r0 + 1) * HID);
        uint32_t a0 = p0[lane * 2],     a1 = p0[lane * 2 + 1];
        uint32_t a2 = p0[64 + lane * 2], a3 = p0[64 + lane * 2 + 1];
        uint32_t c0 = p1[lane * 2],     c1 = p1[lane * 2 + 1];
        uint32_t c2 = p1[64 + lane * 2], c3 = p1[64 + lane * 2 + 1];
        float2 f;
        f = __half22float2(*(__half2*)&a0); h0[0] = f.x; h0[1] = f.y;
        f = __half22float2(*(__half2*)&a1); h0[2] = f.x; h0[3] = f.y;
        f = __half22float2(*(__half2*)&a2); h0[4] = f.x; h0[5] = f.y;
        f = __half22float2(*(__half2*)&a3); h0[6] = f.x; h0[7] = f.y;
        f = __half22float2(*(__half2*)&c0); h1[0] = f.x; h1[1] = f.y;
        f = __half22float2(*(__half2*)&c1); h1[2] = f.x; h1[3] = f.y;
        f = __half22float2(*(__half2*)&c2); h1[4] = f.x; h1[5] = f.y;
        f = __half22float2(*(__half2*)&c3); h1[6] = f.x; h1[7] = f.y;
    }

    for (int c = 0; c < OUTFE; ++c) {
        const float4 wa = *(const float4*)(Ws + c * HID + lane * 4);
        const float4 wb = *(const float4*)(Ws + c * HID + 128 + lane * 4);
        float a0 = h0[0] * wa.x + h0[1] * wa.y + h0[2] * wa.z + h0[3] * wa.w
                 + h0[4] * wb.x + h0[5] * wb.y + h0[6] * wb.z + h0[7] * wb.w;
        float a1 = h1[0] * wa.x + h1[1] * wa.y + h1[2] * wa.z + h1[3] * wa.w
                 + h1[4] * wb.x + h1[5] * wb.y + h1[6] * wb.z + h1[7] * wb.w;
#pragma unroll
        for (int o = 16; o > 0; o >>= 1) {
            a0 += __shfl_xor_sync(0xffffffffu, a0, o);
            a1 += __shfl_xor_sync(0xffffffffu, a1, o);
        }
        if (lane == 0) {
            const float bc = b[c];
            out[(size_t)r0 * OUTFE + c]       = a0 + bc;
            out[(size_t)(r0 + 1) * OUTFE + c] = a1 + bc;
        }
    }
}

// fused2: blocks [0,128) -> gemm3 (EW = tanh(Zh@Wl^T + b_prjL)*outW, grid 2x64)
//         blocks [128,640) -> fc3 (512 blocks)
__global__ void __launch_bounds__(256, 2)
fused2_kernel(const __half* __restrict__ Zh, const __half* __restrict__ Wl,
              const float* __restrict__ b_prjL, const float* __restrict__ outW,
              __half* __restrict__ EW,
              const __half* __restrict__ h, const float* __restrict__ W_fc3,
              const float* __restrict__ b_fc3, float* __restrict__ o_f)
{
    extern __shared__ char dyn[];
    const int b = blockIdx.x;
    if (b < 128) {
        gemm_body<64, 2>(b % 2, b / 2, Zh, Wl, b_prjL, outW, EW, HID, DIN, dyn);
    } else {
        fc3_body(b - 128, h, W_fc3, b_fc3, o_f, dyn);
    }
}

// ---------------------------------------------------------------------------
// All operand conversions in ONE launch (range-dispatched, 256 threads):
//  job0: t -> fp16        (6144 blocks)
//  job1: W_age -> fp16    (576)
//  job2: W_prjT -> fp16   (192)
//  job3: W_prjL -> fp16   (192)
//  job4: gather AGE[Endx] -> fp16 (3072 blocks; item = (row, float4-col))
// ---------------------------------------------------------------------------
#define CV_T   6144
#define CV_WA  576
#define CV_WT  192
#define CV_WL  192
#define CV_G   3072
__global__ void __launch_bounds__(256)
convert_all(const float* __restrict__ t_in, const float* __restrict__ W_age,
            const float* __restrict__ W_prjT, const float* __restrict__ W_prjL,
            const float* __restrict__ AGE, const int* __restrict__ Endx,
            __half* __restrict__ tH, __half* __restrict__ Wa,
            __half* __restrict__ Wt, __half* __restrict__ Wl,
            __half* __restrict__ Ag)
{
    int b = blockIdx.x;
    const float4* src;
    __half2* dst;
    if (b < CV_T) {
        src = (const float4*)t_in;  dst = (__half2*)tH;
    } else if (b < CV_T + CV_WA) {
        b -= CV_T; src = (const float4*)W_age; dst = (__half2*)Wa;
    } else if (b < CV_T + CV_WA + CV_WT) {
        b -= CV_T + CV_WA; src = (const float4*)W_prjT; dst = (__half2*)Wt;
    } else if (b < CV_T + CV_WA + CV_WT + CV_WL) {
        b -= CV_T + CV_WA + CV_WT; src = (const float4*)W_prjL; dst = (__half2*)Wl;
    } else {
        const int i = (b - (CV_T + CV_WA + CV_WT + CV_WL)) * 256 + threadIdx.x;
        const int m = i / 192, c = i % 192;
        const int r = Endx[m];
        float4 v = ((const float4*)(AGE + (size_t)r * DIN))[c];
        __half2* o = (__half2*)(Ag + (size_t)m * DIN) + 2 * c;
        o[0] = __floats2half2_rn(v.x, v.y);
        o[1] = __floats2half2_rn(v.z, v.w);
        return;
    }
    const int i = b * 256 + threadIdx.x;
    float4 v = src[i];
    dst[2 * i]     = __floats2half2_rn(v.x, v.y);
    dst[2 * i + 1] = __floats2half2_rn(v.z, v.w);
}

// ---------------------------------------------------------------------------
// Per-row minmax scale + L2 normalize (fp32 in, fp16 out).
// ---------------------------------------------------------------------------
__global__ void rownorm_kernel(const float* __restrict__ Z, __half* __restrict__ Zh)
{
    __shared__ float shA[8], shB[8];
    const int t = threadIdx.x;
    const float* z = Z + (size_t)blockIdx.x * DIN;
    __half* zo = Zh + (size_t)blockIdx.x * DIN;

    float v0 = z[t], v1 = z[t + 256], v2 = z[t + 512];

    float mn = fminf(v0, fminf(v1, v2));
    float mx = fmaxf(v0, fmaxf(v1, v2));
#pragma unroll
    for (int o = 16; o > 0; o >>= 1) {
        mn = fminf(mn, __shfl_xor_sync(0xffffffffu, mn, o));
        mx = fmaxf(mx, __shfl_xor_sync(0xffffffffu, mx, o));
    }
    if ((t & 31) == 0) { shA[t >> 5] = mn; shB[t >> 5] = mx; }
    __syncthreads();
    float rmn = shA[0], rmx = shB[0];
#pragma unroll
    for (int i = 1; i < 8; ++i) { rmn = fminf(rmn, shA[i]); rmx = fmaxf(rmx, shB[i]); }

    const float sc = 1.f / (rmx - rmn);
    v0 = (v0 - rmn) * sc;
    v1 = (v1 - rmn) * sc;
    v2 = (v2 - rmn) * sc;

    float ss = v0 * v0 + v1 * v1 + v2 * v2;
#pragma unroll
    for (int o = 16; o > 0; o >>= 1)
        ss += __shfl_xor_sync(0xffffffffu, ss, o);
    __syncthreads();
    if ((t & 31) == 0) shA[t >> 5] = ss;
    __syncthreads();
    float tot = 0.f;
#pragma unroll
    for (int i = 0; i < 8; ++i) tot += shA[i];

    const float inv = 1.f / fmaxf(sqrtf(tot), 1e-12f);
    zo[t]       = __float2half(v0 * inv);
    zo[t + 256] = __float2half(v1 * inv);
    zo[t + 512] = __float2half(v2 * inv);
}

// ---------------------------------------------------------------------------
extern "C" void kernel_launch(void* const* d_in, const int* in_sizes, int n_in,
                              void* d_out, int out_size)
{
    const float* t_in   = (const float*)d_in[0];
    const float* AGE    = (const float*)d_in[1];
    const int*   Endx   = (const int*)  d_in[2];
    const float* W_age  = (const float*)d_in[3];
    const float* b_age  = (const float*)d_in[4];
    const float* W_prjT = (const float*)d_in[5];
    const float* b_prjT = (const float*)d_in[6];
    const float* W_prjL = (const float*)d_in[7];
    const float* b_prjL = (const float*)d_in[8];
    const float* outW   = (const float*)d_in[9];
    const float* outb   = (const float*)d_in[10];
    const float* W_fc3  = (const float*)d_in[11];
    const float* b_fc3  = (const float*)d_in[12];

    float* o_c = (float*)d_out;
    float* o_f = o_c + (size_t)NN * MM;

    float *Z;
    __half *Zh, *EW, *h, *tH, *Ag, *Wa, *Wt, *Wl;
    cudaGetSymbolAddress((void**)&Z,  g_Z);
    cudaGetSymbolAddress((void**)&Zh, g_Zh);
    cudaGetSymbolAddress((void**)&EW, g_EW);
    cudaGetSymbolAddress((void**)&h,  g_h);
    cudaGetSymbolAddress((void**)&tH, g_t);
    cudaGetSymbolAddress((void**)&Ag, g_Ag);
    cudaGetSymbolAddress((void**)&Wa, g_Wa);
    cudaGetSymbolAddress((void**)&Wt, g_Wt);
    cudaGetSymbolAddress((void**)&Wl, g_Wl);

    constexpr int SMEM128 = 3 * 32768 + 1024;   // BM=128 stage set
    constexpr int SMEM64  = 3 * 24576 + 1024;   // BM=64 stage set (>= 51200 for fc3 W)
    cudaFuncSetAttribute(gemm_oc,       cudaFuncAttributeMaxDynamicSharedMemorySize, SMEM128);
    cudaFuncSetAttribute(fused1_kernel, cudaFuncAttributeMaxDynamicSharedMemorySize, SMEM64);
    cudaFuncSetAttribute(fused2_kernel, cudaFuncAttributeMaxDynamicSharedMemorySize, SMEM64);

    // 1) all operand conversions (5 jobs, 1 launch)
    convert_all<<<CV_T + CV_WA + CV_WT + CV_WL + CV_G, 256>>>(
        t_in, W_age, W_prjT, W_prjL, AGE, Endx, tH, Wa, Wt, Wl, Ag);

    // 2) gemm1 (Z) + gemm4 (h) fused — 640 blocks
    fused1_kernel<<<640, 256, SMEM64>>>(Ag, Wa, b_age, Z, tH, Wt, b_prjT, h);

    // 3) per-row minmax scale + L2 normalize -> fp16
    rownorm_kernel<<<MM, 256>>>(Z, Zh);

    // 4) gemm3 (EW) + fc3 (o_f) fused — 640 blocks
    fused2_kernel<<<640, 256, SMEM64>>>(Zh, Wl, b_prjL, outW, EW, h, W_fc3, b_fc3, o_f);

    // 5) o_c = h @ EW^T + outb — 2048 blocks
    gemm_oc<<<dim3(MM / 128, NN / 128), 256, SMEM128>>>(h, EW, outb, o_c, MM, HID);
}